// round 1
// baseline (speedup 1.0000x reference)
#include <cuda_runtime.h>

#define NTOK 16384
#define BDIM 8
#define LSEQ 2048
#define DM   512
#define HID  1024

#define BM 128
#define BN 64
#define BK 16
#define PADA (BM + 4)
#define PADB (BN + 4)

// Scratch (device globals: allocation-free)
__device__ float g_Hre[(size_t)NTOK * HID];
__device__ float g_Him[(size_t)NTOK * HID];
__device__ float g_y[(size_t)NTOK * DM];
__device__ float g_lre[HID], g_lim[HID], g_gam[HID];

// ---------------------------------------------------------------------------
// Precompute lambda (complex) and gamma from params_log = [nu_log; theta_log; gamma_log]
// ---------------------------------------------------------------------------
__global__ void precompute_kernel(const float* __restrict__ plog) {
    int h = threadIdx.x;
    float nu = expf(plog[h]);
    float th = expf(plog[HID + h]);
    float ga = expf(plog[2 * HID + h]);
    float er = expf(-nu);
    g_lre[h] = er * cosf(th);
    g_lim[h] = er * sinf(th);
    g_gam[h] = ga;
}

// ---------------------------------------------------------------------------
// Input projection: h = (X @ W_in^T + b_in) * gamma  (re and im fused, share X tile)
// X: [NTOK, DM] row-major, W: [HID, DM] row-major (K contiguous both sides: NT GEMM)
// ---------------------------------------------------------------------------
__global__ __launch_bounds__(256, 2)
void proj_in_kernel(const float* __restrict__ X, const float* __restrict__ Wre,
                    const float* __restrict__ Wim, const float* __restrict__ bre,
                    const float* __restrict__ bim) {
    __shared__ float As[BK][PADA];
    __shared__ float Br[BK][PADB];
    __shared__ float Bi[BK][PADB];

    const int tid = threadIdx.x;
    const int bm = blockIdx.x * BM;
    const int bn = blockIdx.y * BN;
    const int ty = tid >> 4;      // 0..15, 8 rows each
    const int tx = tid & 15;      // 0..15, 4 cols each

    const int ar = tid >> 2;         // 0..63
    const int ac = (tid & 3) * 4;    // 0,4,8,12

    float accR[8][4];
    float accI[8][4];
#pragma unroll
    for (int i = 0; i < 8; i++)
#pragma unroll
        for (int j = 0; j < 4; j++) { accR[i][j] = 0.f; accI[i][j] = 0.f; }

    for (int k0 = 0; k0 < DM; k0 += BK) {
        // load A tile (128 x 16), transposed into smem
#pragma unroll
        for (int i = 0; i < 2; i++) {
            int r = ar + i * 64;
            float4 v = *reinterpret_cast<const float4*>(X + (size_t)(bm + r) * DM + k0 + ac);
            As[ac + 0][r] = v.x; As[ac + 1][r] = v.y;
            As[ac + 2][r] = v.z; As[ac + 3][r] = v.w;
        }
        // load W tiles (64 x 16)
        {
            float4 v = *reinterpret_cast<const float4*>(Wre + (size_t)(bn + ar) * DM + k0 + ac);
            Br[ac + 0][ar] = v.x; Br[ac + 1][ar] = v.y;
            Br[ac + 2][ar] = v.z; Br[ac + 3][ar] = v.w;
            float4 w = *reinterpret_cast<const float4*>(Wim + (size_t)(bn + ar) * DM + k0 + ac);
            Bi[ac + 0][ar] = w.x; Bi[ac + 1][ar] = w.y;
            Bi[ac + 2][ar] = w.z; Bi[ac + 3][ar] = w.w;
        }
        __syncthreads();
#pragma unroll
        for (int k = 0; k < BK; k++) {
            float4 a0 = *reinterpret_cast<const float4*>(&As[k][ty * 8]);
            float4 a1 = *reinterpret_cast<const float4*>(&As[k][ty * 8 + 4]);
            float4 brv4 = *reinterpret_cast<const float4*>(&Br[k][tx * 4]);
            float4 biv4 = *reinterpret_cast<const float4*>(&Bi[k][tx * 4]);
            float a[8] = {a0.x, a0.y, a0.z, a0.w, a1.x, a1.y, a1.z, a1.w};
            float brv[4] = {brv4.x, brv4.y, brv4.z, brv4.w};
            float biv[4] = {biv4.x, biv4.y, biv4.z, biv4.w};
#pragma unroll
            for (int i = 0; i < 8; i++)
#pragma unroll
                for (int j = 0; j < 4; j++) {
                    accR[i][j] = fmaf(a[i], brv[j], accR[i][j]);
                    accI[i][j] = fmaf(a[i], biv[j], accI[i][j]);
                }
        }
        __syncthreads();
    }

    // epilogue: (acc + b) * gamma, vectorized stores
    const int n0 = bn + tx * 4;
    float ga[4], b1[4], b2[4];
#pragma unroll
    for (int j = 0; j < 4; j++) {
        ga[j] = g_gam[n0 + j]; b1[j] = bre[n0 + j]; b2[j] = bim[n0 + j];
    }
#pragma unroll
    for (int i = 0; i < 8; i++) {
        int m = bm + ty * 8 + i;
        float4 vr, vi;
        vr.x = (accR[i][0] + b1[0]) * ga[0]; vr.y = (accR[i][1] + b1[1]) * ga[1];
        vr.z = (accR[i][2] + b1[2]) * ga[2]; vr.w = (accR[i][3] + b1[3]) * ga[3];
        vi.x = (accI[i][0] + b2[0]) * ga[0]; vi.y = (accI[i][1] + b2[1]) * ga[1];
        vi.z = (accI[i][2] + b2[2]) * ga[2]; vi.w = (accI[i][3] + b2[3]) * ga[3];
        *reinterpret_cast<float4*>(&g_Hre[(size_t)m * HID + n0]) = vr;
        *reinterpret_cast<float4*>(&g_Him[(size_t)m * HID + n0]) = vi;
    }
}

// ---------------------------------------------------------------------------
// Sequential LRU scan over L per (b,h) chain: h[t] = u[t] + lambda*m[t-1]*h[t-1]
// 8192 threads; software-prefetch next U elements to hide DRAM latency.
// ---------------------------------------------------------------------------
__global__ void scan_kernel(const float* __restrict__ mask) {
    int idx = blockIdx.x * blockDim.x + threadIdx.x;
    int b = idx >> 10;
    int h = idx & (HID - 1);
    const float lre = g_lre[h], lim = g_lim[h];
    const size_t base = (size_t)b * LSEQ * HID + h;
    float pre = 0.f, pim = 0.f;
    const int U = 8;
    float nre[U], nim[U];
#pragma unroll
    for (int j = 0; j < U; j++) {
        nre[j] = g_Hre[base + (size_t)j * HID];
        nim[j] = g_Him[base + (size_t)j * HID];
    }
    for (int l0 = 0; l0 < LSEQ; l0 += U) {
        float cre[U], cim[U];
#pragma unroll
        for (int j = 0; j < U; j++) { cre[j] = nre[j]; cim[j] = nim[j]; }
        if (l0 + U < LSEQ) {
#pragma unroll
            for (int j = 0; j < U; j++) {
                nre[j] = g_Hre[base + (size_t)(l0 + U + j) * HID];
                nim[j] = g_Him[base + (size_t)(l0 + U + j) * HID];
            }
        }
#pragma unroll
        for (int j = 0; j < U; j++) {
            int l = l0 + j;
            if (l > 0) {
                float m = mask[b * LSEQ + l - 1];
                float ar = lre * m, ai = lim * m;
                float r  = cre[j] + ar * pre - ai * pim;
                float im = cim[j] + ar * pim + ai * pre;
                g_Hre[base + (size_t)l * HID] = r;
                g_Him[base + (size_t)l * HID] = im;
                pre = r; pim = im;
            } else {
                pre = cre[j]; pim = cim[j];
            }
        }
    }
}

// ---------------------------------------------------------------------------
// Output projection: y = Re(h @ W_out^T) + b_out_re + x
// = Hre @ Wout_re^T - Him @ Wout_im^T  (fused into one K loop)
// ---------------------------------------------------------------------------
__global__ __launch_bounds__(256, 2)
void proj_out_kernel(const float* __restrict__ Wre, const float* __restrict__ Wim,
                     const float* __restrict__ bout, const float* __restrict__ X) {
    __shared__ float Ar[BK][PADA];
    __shared__ float Ai[BK][PADA];
    __shared__ float Br[BK][PADB];
    __shared__ float Bi[BK][PADB];

    const int tid = threadIdx.x;
    const int bm = blockIdx.x * BM;
    const int bn = blockIdx.y * BN;
    const int ty = tid >> 4;
    const int tx = tid & 15;
    const int ar = tid >> 2;
    const int ac = (tid & 3) * 4;

    float acc[8][4];
#pragma unroll
    for (int i = 0; i < 8; i++)
#pragma unroll
        for (int j = 0; j < 4; j++) acc[i][j] = 0.f;

    for (int k0 = 0; k0 < HID; k0 += BK) {
#pragma unroll
        for (int i = 0; i < 2; i++) {
            int r = ar + i * 64;
            float4 v = *reinterpret_cast<const float4*>(&g_Hre[(size_t)(bm + r) * HID + k0 + ac]);
            Ar[ac + 0][r] = v.x; Ar[ac + 1][r] = v.y;
            Ar[ac + 2][r] = v.z; Ar[ac + 3][r] = v.w;
            float4 w = *reinterpret_cast<const float4*>(&g_Him[(size_t)(bm + r) * HID + k0 + ac]);
            Ai[ac + 0][r] = w.x; Ai[ac + 1][r] = w.y;
            Ai[ac + 2][r] = w.z; Ai[ac + 3][r] = w.w;
        }
        {
            float4 v = *reinterpret_cast<const float4*>(Wre + (size_t)(bn + ar) * HID + k0 + ac);
            Br[ac + 0][ar] = v.x; Br[ac + 1][ar] = v.y;
            Br[ac + 2][ar] = v.z; Br[ac + 3][ar] = v.w;
            float4 w = *reinterpret_cast<const float4*>(Wim + (size_t)(bn + ar) * HID + k0 + ac);
            Bi[ac + 0][ar] = w.x; Bi[ac + 1][ar] = w.y;
            Bi[ac + 2][ar] = w.z; Bi[ac + 3][ar] = w.w;
        }
        __syncthreads();
#pragma unroll
        for (int k = 0; k < BK; k++) {
            float4 a0 = *reinterpret_cast<const float4*>(&Ar[k][ty * 8]);
            float4 a1 = *reinterpret_cast<const float4*>(&Ar[k][ty * 8 + 4]);
            float4 c0 = *reinterpret_cast<const float4*>(&Ai[k][ty * 8]);
            float4 c1 = *reinterpret_cast<const float4*>(&Ai[k][ty * 8 + 4]);
            float4 brv4 = *reinterpret_cast<const float4*>(&Br[k][tx * 4]);
            float4 biv4 = *reinterpret_cast<const float4*>(&Bi[k][tx * 4]);
            float areg[8] = {a0.x, a0.y, a0.z, a0.w, a1.x, a1.y, a1.z, a1.w};
            float ireg[8] = {c0.x, c0.y, c0.z, c0.w, c1.x, c1.y, c1.z, c1.w};
            float brv[4] = {brv4.x, brv4.y, brv4.z, brv4.w};
            float biv[4] = {biv4.x, biv4.y, biv4.z, biv4.w};
#pragma unroll
            for (int i = 0; i < 8; i++)
#pragma unroll
                for (int j = 0; j < 4; j++) {
                    acc[i][j] = fmaf(areg[i], brv[j], acc[i][j]);
                    acc[i][j] = fmaf(-ireg[i], biv[j], acc[i][j]);
                }
        }
        __syncthreads();
    }

    const int n0 = bn + tx * 4;
    float bo[4];
#pragma unroll
    for (int j = 0; j < 4; j++) bo[j] = bout[n0 + j];
#pragma unroll
    for (int i = 0; i < 8; i++) {
        int m = bm + ty * 8 + i;
        float4 xr = *reinterpret_cast<const float4*>(X + (size_t)m * DM + n0);
        float4 v;
        v.x = acc[i][0] + bo[0] + xr.x;
        v.y = acc[i][1] + bo[1] + xr.y;
        v.z = acc[i][2] + bo[2] + xr.z;
        v.w = acc[i][3] + bo[3] + xr.w;
        *reinterpret_cast<float4*>(&g_y[(size_t)m * DM + n0]) = v;
    }
}

// ---------------------------------------------------------------------------
// LayerNorm over D=512 per row; one warp per row.
// ---------------------------------------------------------------------------
__global__ void ln_kernel(const float* __restrict__ lnw, const float* __restrict__ lnb,
                          float* __restrict__ out) {
    int row = blockIdx.x * 8 + (threadIdx.x >> 5);
    int lane = threadIdx.x & 31;
    const float* yr = g_y + (size_t)row * DM;
    float v[16];
    float s = 0.f;
#pragma unroll
    for (int i = 0; i < 16; i++) { v[i] = yr[lane + 32 * i]; s += v[i]; }
#pragma unroll
    for (int o = 16; o > 0; o >>= 1) s += __shfl_xor_sync(0xffffffffu, s, o);
    float mean = s * (1.0f / DM);
    float q = 0.f;
#pragma unroll
    for (int i = 0; i < 16; i++) { float d = v[i] - mean; q = fmaf(d, d, q); }
#pragma unroll
    for (int o = 16; o > 0; o >>= 1) q += __shfl_xor_sync(0xffffffffu, q, o);
    float inv = rsqrtf(q * (1.0f / DM) + 1e-5f);
#pragma unroll
    for (int i = 0; i < 16; i++) {
        int c = lane + 32 * i;
        out[(size_t)row * DM + c] = (v[i] - mean) * inv * lnw[c] + lnb[c];
    }
}

// ---------------------------------------------------------------------------
extern "C" void kernel_launch(void* const* d_in, const int* in_sizes, int n_in,
                              void* d_out, int out_size) {
    const float* x    = (const float*)d_in[0];
    const float* mask = (const float*)d_in[1];
    const float* plog = (const float*)d_in[2];
    const float* Wre  = (const float*)d_in[3];
    const float* Wim  = (const float*)d_in[4];
    const float* bre  = (const float*)d_in[5];
    const float* bim  = (const float*)d_in[6];
    const float* Wor  = (const float*)d_in[7];
    const float* Woi  = (const float*)d_in[8];
    const float* bor  = (const float*)d_in[9];
    // d_in[10] = b_out_im (unused: only real part of output projection survives)
    const float* lnw  = (const float*)d_in[11];
    const float* lnb  = (const float*)d_in[12];
    float* out = (float*)d_out;

    precompute_kernel<<<1, HID>>>(plog);

    dim3 g1(NTOK / BM, HID / BN);
    proj_in_kernel<<<g1, 256>>>(x, Wre, Wim, bre, bim);

    scan_kernel<<<(BDIM * HID) / 256, 256>>>(mask);

    dim3 g2(NTOK / BM, DM / BN);
    proj_out_kernel<<<g2, 256>>>(Wor, Woi, bor, x);

    ln_kernel<<<NTOK / 8, 256>>>(lnw, lnb, out);
}

// round 2
// speedup vs baseline: 1.0037x; 1.0037x over previous
#include <cuda_runtime.h>

#define NTOK 16384
#define BDIM 8
#define LSEQ 2048
#define DM   512
#define HID  1024

#define BM 128
#define BN 64
#define BK 16
#define PADA (BM + 4)
#define PADB (BN + 4)

// Scratch (device globals: allocation-free)
__device__ float g_Hre[(size_t)NTOK * HID];
__device__ float g_Him[(size_t)NTOK * HID];
__device__ float g_y[(size_t)NTOK * DM];
__device__ float g_lre[HID], g_lim[HID], g_gam[HID];

// ---------------------------------------------------------------------------
// Precompute lambda (complex) and gamma from params_log = [nu_log; theta_log; gamma_log]
// ---------------------------------------------------------------------------
__global__ void precompute_kernel(const float* __restrict__ plog) {
    int h = threadIdx.x;
    float nu = expf(plog[h]);
    float th = expf(plog[HID + h]);
    float ga = expf(plog[2 * HID + h]);
    float er = expf(-nu);
    g_lre[h] = er * cosf(th);
    g_lim[h] = er * sinf(th);
    g_gam[h] = ga;
}

// ---------------------------------------------------------------------------
// Input projection: h = (X @ W_in^T + b_in) * gamma  (re and im fused, share X tile)
// X: [NTOK, DM] row-major, W: [HID, DM] row-major (K contiguous both sides: NT GEMM)
// ---------------------------------------------------------------------------
__global__ __launch_bounds__(256, 2)
void proj_in_kernel(const float* __restrict__ X, const float* __restrict__ Wre,
                    const float* __restrict__ Wim, const float* __restrict__ bre,
                    const float* __restrict__ bim) {
    __shared__ float As[BK][PADA];
    __shared__ float Br[BK][PADB];
    __shared__ float Bi[BK][PADB];

    const int tid = threadIdx.x;
    const int bm = blockIdx.x * BM;
    const int bn = blockIdx.y * BN;
    const int ty = tid >> 4;      // 0..15, 8 rows each
    const int tx = tid & 15;      // 0..15, 4 cols each

    const int ar = tid >> 2;         // 0..63
    const int ac = (tid & 3) * 4;    // 0,4,8,12

    float accR[8][4];
    float accI[8][4];
#pragma unroll
    for (int i = 0; i < 8; i++)
#pragma unroll
        for (int j = 0; j < 4; j++) { accR[i][j] = 0.f; accI[i][j] = 0.f; }

    for (int k0 = 0; k0 < DM; k0 += BK) {
        // load A tile (128 x 16), transposed into smem
#pragma unroll
        for (int i = 0; i < 2; i++) {
            int r = ar + i * 64;
            float4 v = *reinterpret_cast<const float4*>(X + (size_t)(bm + r) * DM + k0 + ac);
            As[ac + 0][r] = v.x; As[ac + 1][r] = v.y;
            As[ac + 2][r] = v.z; As[ac + 3][r] = v.w;
        }
        // load W tiles (64 x 16)
        {
            float4 v = *reinterpret_cast<const float4*>(Wre + (size_t)(bn + ar) * DM + k0 + ac);
            Br[ac + 0][ar] = v.x; Br[ac + 1][ar] = v.y;
            Br[ac + 2][ar] = v.z; Br[ac + 3][ar] = v.w;
            float4 w = *reinterpret_cast<const float4*>(Wim + (size_t)(bn + ar) * DM + k0 + ac);
            Bi[ac + 0][ar] = w.x; Bi[ac + 1][ar] = w.y;
            Bi[ac + 2][ar] = w.z; Bi[ac + 3][ar] = w.w;
        }
        __syncthreads();
#pragma unroll
        for (int k = 0; k < BK; k++) {
            float4 a0 = *reinterpret_cast<const float4*>(&As[k][ty * 8]);
            float4 a1 = *reinterpret_cast<const float4*>(&As[k][ty * 8 + 4]);
            float4 brv4 = *reinterpret_cast<const float4*>(&Br[k][tx * 4]);
            float4 biv4 = *reinterpret_cast<const float4*>(&Bi[k][tx * 4]);
            float a[8] = {a0.x, a0.y, a0.z, a0.w, a1.x, a1.y, a1.z, a1.w};
            float brv[4] = {brv4.x, brv4.y, brv4.z, brv4.w};
            float biv[4] = {biv4.x, biv4.y, biv4.z, biv4.w};
#pragma unroll
            for (int i = 0; i < 8; i++)
#pragma unroll
                for (int j = 0; j < 4; j++) {
                    accR[i][j] = fmaf(a[i], brv[j], accR[i][j]);
                    accI[i][j] = fmaf(a[i], biv[j], accI[i][j]);
                }
        }
        __syncthreads();
    }

    // epilogue: (acc + b) * gamma, vectorized stores
    const int n0 = bn + tx * 4;
    float ga[4], b1[4], b2[4];
#pragma unroll
    for (int j = 0; j < 4; j++) {
        ga[j] = g_gam[n0 + j]; b1[j] = bre[n0 + j]; b2[j] = bim[n0 + j];
    }
#pragma unroll
    for (int i = 0; i < 8; i++) {
        int m = bm + ty * 8 + i;
        float4 vr, vi;
        vr.x = (accR[i][0] + b1[0]) * ga[0]; vr.y = (accR[i][1] + b1[1]) * ga[1];
        vr.z = (accR[i][2] + b1[2]) * ga[2]; vr.w = (accR[i][3] + b1[3]) * ga[3];
        vi.x = (accI[i][0] + b2[0]) * ga[0]; vi.y = (accI[i][1] + b2[1]) * ga[1];
        vi.z = (accI[i][2] + b2[2]) * ga[2]; vi.w = (accI[i][3] + b2[3]) * ga[3];
        *reinterpret_cast<float4*>(&g_Hre[(size_t)m * HID + n0]) = vr;
        *reinterpret_cast<float4*>(&g_Him[(size_t)m * HID + n0]) = vi;
    }
}

// ---------------------------------------------------------------------------
// Sequential LRU scan over L per (b,h) chain: h[t] = u[t] + lambda*m[t-1]*h[t-1]
// 8192 threads; software-prefetch next U elements to hide DRAM latency.
// ---------------------------------------------------------------------------
__global__ void scan_kernel(const float* __restrict__ mask) {
    int idx = blockIdx.x * blockDim.x + threadIdx.x;
    int b = idx >> 10;
    int h = idx & (HID - 1);
    const float lre = g_lre[h], lim = g_lim[h];
    const size_t base = (size_t)b * LSEQ * HID + h;
    float pre = 0.f, pim = 0.f;
    const int U = 8;
    float nre[U], nim[U];
#pragma unroll
    for (int j = 0; j < U; j++) {
        nre[j] = g_Hre[base + (size_t)j * HID];
        nim[j] = g_Him[base + (size_t)j * HID];
    }
    for (int l0 = 0; l0 < LSEQ; l0 += U) {
        float cre[U], cim[U];
#pragma unroll
        for (int j = 0; j < U; j++) { cre[j] = nre[j]; cim[j] = nim[j]; }
        if (l0 + U < LSEQ) {
#pragma unroll
            for (int j = 0; j < U; j++) {
                nre[j] = g_Hre[base + (size_t)(l0 + U + j) * HID];
                nim[j] = g_Him[base + (size_t)(l0 + U + j) * HID];
            }
        }
#pragma unroll
        for (int j = 0; j < U; j++) {
            int l = l0 + j;
            if (l > 0) {
                float m = mask[b * LSEQ + l - 1];
                float ar = lre * m, ai = lim * m;
                float r  = cre[j] + ar * pre - ai * pim;
                float im = cim[j] + ar * pim + ai * pre;
                g_Hre[base + (size_t)l * HID] = r;
                g_Him[base + (size_t)l * HID] = im;
                pre = r; pim = im;
            } else {
                pre = cre[j]; pim = cim[j];
            }
        }
    }
}

// ---------------------------------------------------------------------------
// Output projection: y = Re(h @ W_out^T) + b_out_re + x
// = Hre @ Wout_re^T - Him @ Wout_im^T  (fused into one K loop)
// ---------------------------------------------------------------------------
__global__ __launch_bounds__(256, 2)
void proj_out_kernel(const float* __restrict__ Wre, const float* __restrict__ Wim,
                     const float* __restrict__ bout, const float* __restrict__ X) {
    __shared__ float Ar[BK][PADA];
    __shared__ float Ai[BK][PADA];
    __shared__ float Br[BK][PADB];
    __shared__ float Bi[BK][PADB];

    const int tid = threadIdx.x;
    const int bm = blockIdx.x * BM;
    const int bn = blockIdx.y * BN;
    const int ty = tid >> 4;
    const int tx = tid & 15;
    const int ar = tid >> 2;
    const int ac = (tid & 3) * 4;

    float acc[8][4];
#pragma unroll
    for (int i = 0; i < 8; i++)
#pragma unroll
        for (int j = 0; j < 4; j++) acc[i][j] = 0.f;

    for (int k0 = 0; k0 < HID; k0 += BK) {
#pragma unroll
        for (int i = 0; i < 2; i++) {
            int r = ar + i * 64;
            float4 v = *reinterpret_cast<const float4*>(&g_Hre[(size_t)(bm + r) * HID + k0 + ac]);
            Ar[ac + 0][r] = v.x; Ar[ac + 1][r] = v.y;
            Ar[ac + 2][r] = v.z; Ar[ac + 3][r] = v.w;
            float4 w = *reinterpret_cast<const float4*>(&g_Him[(size_t)(bm + r) * HID + k0 + ac]);
            Ai[ac + 0][r] = w.x; Ai[ac + 1][r] = w.y;
            Ai[ac + 2][r] = w.z; Ai[ac + 3][r] = w.w;
        }
        {
            float4 v = *reinterpret_cast<const float4*>(Wre + (size_t)(bn + ar) * HID + k0 + ac);
            Br[ac + 0][ar] = v.x; Br[ac + 1][ar] = v.y;
            Br[ac + 2][ar] = v.z; Br[ac + 3][ar] = v.w;
            float4 w = *reinterpret_cast<const float4*>(Wim + (size_t)(bn + ar) * HID + k0 + ac);
            Bi[ac + 0][ar] = w.x; Bi[ac + 1][ar] = w.y;
            Bi[ac + 2][ar] = w.z; Bi[ac + 3][ar] = w.w;
        }
        __syncthreads();
#pragma unroll
        for (int k = 0; k < BK; k++) {
            float4 a0 = *reinterpret_cast<const float4*>(&Ar[k][ty * 8]);
            float4 a1 = *reinterpret_cast<const float4*>(&Ar[k][ty * 8 + 4]);
            float4 c0 = *reinterpret_cast<const float4*>(&Ai[k][ty * 8]);
            float4 c1 = *reinterpret_cast<const float4*>(&Ai[k][ty * 8 + 4]);
            float4 brv4 = *reinterpret_cast<const float4*>(&Br[k][tx * 4]);
            float4 biv4 = *reinterpret_cast<const float4*>(&Bi[k][tx * 4]);
            float areg[8] = {a0.x, a0.y, a0.z, a0.w, a1.x, a1.y, a1.z, a1.w};
            float ireg[8] = {c0.x, c0.y, c0.z, c0.w, c1.x, c1.y, c1.z, c1.w};
            float brv[4] = {brv4.x, brv4.y, brv4.z, brv4.w};
            float biv[4] = {biv4.x, biv4.y, biv4.z, biv4.w};
#pragma unroll
            for (int i = 0; i < 8; i++)
#pragma unroll
                for (int j = 0; j < 4; j++) {
                    acc[i][j] = fmaf(areg[i], brv[j], acc[i][j]);
                    acc[i][j] = fmaf(-ireg[i], biv[j], acc[i][j]);
                }
        }
        __syncthreads();
    }

    const int n0 = bn + tx * 4;
    float bo[4];
#pragma unroll
    for (int j = 0; j < 4; j++) bo[j] = bout[n0 + j];
#pragma unroll
    for (int i = 0; i < 8; i++) {
        int m = bm + ty * 8 + i;
        float4 xr = *reinterpret_cast<const float4*>(X + (size_t)m * DM + n0);
        float4 v;
        v.x = acc[i][0] + bo[0] + xr.x;
        v.y = acc[i][1] + bo[1] + xr.y;
        v.z = acc[i][2] + bo[2] + xr.z;
        v.w = acc[i][3] + bo[3] + xr.w;
        *reinterpret_cast<float4*>(&g_y[(size_t)m * DM + n0]) = v;
    }
}

// ---------------------------------------------------------------------------
// LayerNorm over D=512 per row; one warp per row.
// ---------------------------------------------------------------------------
__global__ void ln_kernel(const float* __restrict__ lnw, const float* __restrict__ lnb,
                          float* __restrict__ out) {
    int row = blockIdx.x * 8 + (threadIdx.x >> 5);
    int lane = threadIdx.x & 31;
    const float* yr = g_y + (size_t)row * DM;
    float v[16];
    float s = 0.f;
#pragma unroll
    for (int i = 0; i < 16; i++) { v[i] = yr[lane + 32 * i]; s += v[i]; }
#pragma unroll
    for (int o = 16; o > 0; o >>= 1) s += __shfl_xor_sync(0xffffffffu, s, o);
    float mean = s * (1.0f / DM);
    float q = 0.f;
#pragma unroll
    for (int i = 0; i < 16; i++) { float d = v[i] - mean; q = fmaf(d, d, q); }
#pragma unroll
    for (int o = 16; o > 0; o >>= 1) q += __shfl_xor_sync(0xffffffffu, q, o);
    float inv = rsqrtf(q * (1.0f / DM) + 1e-5f);
#pragma unroll
    for (int i = 0; i < 16; i++) {
        int c = lane + 32 * i;
        out[(size_t)row * DM + c] = (v[i] - mean) * inv * lnw[c] + lnb[c];
    }
}

// ---------------------------------------------------------------------------
extern "C" void kernel_launch(void* const* d_in, const int* in_sizes, int n_in,
                              void* d_out, int out_size) {
    const float* x    = (const float*)d_in[0];
    const float* mask = (const float*)d_in[1];
    const float* plog = (const float*)d_in[2];
    const float* Wre  = (const float*)d_in[3];
    const float* Wim  = (const float*)d_in[4];
    const float* bre  = (const float*)d_in[5];
    const float* bim  = (const float*)d_in[6];
    const float* Wor  = (const float*)d_in[7];
    const float* Woi  = (const float*)d_in[8];
    const float* bor  = (const float*)d_in[9];
    // d_in[10] = b_out_im (unused: only real part of output projection survives)
    const float* lnw  = (const float*)d_in[11];
    const float* lnb  = (const float*)d_in[12];
    float* out = (float*)d_out;

    precompute_kernel<<<1, HID>>>(plog);

    dim3 g1(NTOK / BM, HID / BN);
    proj_in_kernel<<<g1, 256>>>(x, Wre, Wim, bre, bim);

    scan_kernel<<<(BDIM * HID) / 256, 256>>>(mask);

    dim3 g2(NTOK / BM, DM / BN);
    proj_out_kernel<<<g2, 256>>>(Wor, Woi, bor, x);

    ln_kernel<<<NTOK / 8, 256>>>(lnw, lnb, out);
}

// round 7
// speedup vs baseline: 2.6330x; 2.6234x over previous
#include <cuda_runtime.h>
#include <cstdint>

#define NTOK 16384
#define BDIM 8
#define LSEQ 2048
#define DM   512
#define HID  1024
#define NTOT 2048   // 2*HID

// ---------------------------------------------------------------------------
// Device-global scratch (allocation-free)
// ---------------------------------------------------------------------------
__device__ float g_X [(size_t)NTOK * DM];    // tf32-rounded X
__device__ float g_W1[(size_t)NTOT * DM];    // [Wre; Wim] rows, tf32-rounded
__device__ float g_Wo[(size_t)DM * NTOT];    // [Wor, -Woi] per row, tf32-rounded
__device__ float g_H [(size_t)NTOK * NTOT];  // per row: [re(0..1023), im(1024..2047)]
__device__ float g_y [(size_t)NTOK * DM];
__device__ float g_lre[HID], g_lim[HID];
__device__ float g_gam2[NTOT], g_bg[NTOT];   // gamma (dup) and bias*gamma (stacked)

__device__ __forceinline__ float tf32r(float x) {
    uint32_t o;
    asm("cvt.rna.tf32.f32 %0, %1;" : "=r"(o) : "f"(x));
    return __uint_as_float(o);
}

// ---------------------------------------------------------------------------
// Precompute: lambda, gamma, fused epilogue constants
// ---------------------------------------------------------------------------
__global__ void precompute_kernel(const float* __restrict__ plog,
                                  const float* __restrict__ bre,
                                  const float* __restrict__ bim) {
    int h = threadIdx.x;  // 1024
    float nu = expf(plog[h]);
    float th = expf(plog[HID + h]);
    float ga = expf(plog[2 * HID + h]);
    float er = expf(-nu);
    g_lre[h] = er * cosf(th);
    g_lim[h] = er * sinf(th);
    g_gam2[h] = ga;  g_gam2[HID + h] = ga;
    g_bg[h] = bre[h] * ga;  g_bg[HID + h] = bim[h] * ga;
}

// ---------------------------------------------------------------------------
// tf32-round pre-passes
// ---------------------------------------------------------------------------
__device__ __forceinline__ float4 tf32r4(float4 v) {
    v.x = tf32r(v.x); v.y = tf32r(v.y); v.z = tf32r(v.z); v.w = tf32r(v.w);
    return v;
}

__global__ void cvt_x_kernel(const float* __restrict__ x) {
    int i = blockIdx.x * 256 + threadIdx.x;  // 2,097,152 float4
    float4 v = reinterpret_cast<const float4*>(x)[i];
    reinterpret_cast<float4*>(g_X)[i] = tf32r4(v);
}

__global__ void cvt_w1_kernel(const float* __restrict__ Wre, const float* __restrict__ Wim) {
    int i = blockIdx.x * 256 + threadIdx.x;  // 131072 float4 per half
    float4 a = reinterpret_cast<const float4*>(Wre)[i];
    float4 b = reinterpret_cast<const float4*>(Wim)[i];
    reinterpret_cast<float4*>(g_W1)[i] = tf32r4(a);
    reinterpret_cast<float4*>(g_W1)[i + 131072] = tf32r4(b);
}

__global__ void cvt_wo_kernel(const float* __restrict__ Wor, const float* __restrict__ Woi) {
    int i = blockIdx.x * 256 + threadIdx.x;  // 262144 float4 total
    int d = i >> 9;          // row (512 float4 per row of 2048 floats)
    int kq = i & 511;
    float4 v;
    if (kq < 256) {
        v = reinterpret_cast<const float4*>(Wor)[d * 256 + kq];
    } else {
        v = reinterpret_cast<const float4*>(Woi)[d * 256 + (kq - 256)];
        v.x = -v.x; v.y = -v.y; v.z = -v.z; v.w = -v.w;
    }
    reinterpret_cast<float4*>(g_Wo)[i] = tf32r4(v);
}

// ---------------------------------------------------------------------------
// TF32 tensor-core GEMM: C[m][n] = sum_k A[m][k]*B[n][k]
// Block tile 128x128, BK=32, 3-stage cp.async, 2x4 warps of 64x32.
// MODE 1: A=g_X, B=g_W1, out g_H with fused (acc*gamma + bias*gamma)
// MODE 2: A=g_H, B=g_Wo, out g_y with fused (+bias +residual)
// ---------------------------------------------------------------------------
#define STAGE_BYTES 16384   // 128 rows * 32 floats * 4B

__device__ __forceinline__ void cp16(uint32_t dst, const float* src) {
    asm volatile("cp.async.cg.shared.global [%0], [%1], 16;" :: "r"(dst), "l"(src));
}

#define LDSM4(R0, R1, R2, R3, addr) \
    asm volatile("ldmatrix.sync.aligned.m8n8.x4.shared.b16 {%0,%1,%2,%3}, [%4];" \
                 : "=r"(R0), "=r"(R1), "=r"(R2), "=r"(R3) : "r"(addr))

#define MMA_TF32(c, a, b0r, b1r) \
    asm volatile("mma.sync.aligned.m16n8k8.row.col.f32.tf32.tf32.f32 " \
                 "{%0,%1,%2,%3}, {%4,%5,%6,%7}, {%8,%9}, {%0,%1,%2,%3};" \
                 : "+f"(c[0]), "+f"(c[1]), "+f"(c[2]), "+f"(c[3]) \
                 : "r"(a[0]), "r"(a[1]), "r"(a[2]), "r"(a[3]), "r"(b0r), "r"(b1r))

template<int K, int MODE>
__global__ __launch_bounds__(256, 2)
void gemm_tf32(const float* __restrict__ bias, const float* __restrict__ resid) {
    extern __shared__ float smem[];
    const float* A    = (MODE == 1) ? g_X  : g_H;
    const float* Bmat = (MODE == 1) ? g_W1 : g_Wo;

    const int tid  = threadIdx.x;
    const int lane = tid & 31;
    const int wid  = tid >> 5;
    const int wm   = (wid >> 2) * 64;   // warp m offset (0/64)
    const int wn   = (wid & 3) * 32;    // warp n offset (0/32/64/96)
    const int bm   = blockIdx.x * 128;
    const int bn   = blockIdx.y * 128;

    uint32_t sm_base = (uint32_t)__cvta_generic_to_shared(smem);
    uint32_t sA0 = sm_base;
    uint32_t sB0 = sm_base + 3 * STAGE_BYTES;

    float acc[4][4][4];
#pragma unroll
    for (int i = 0; i < 4; i++)
#pragma unroll
        for (int j = 0; j < 4; j++)
#pragma unroll
            for (int e = 0; e < 4; e++) acc[i][j][e] = 0.f;

    const int KT = K / 32;

    // ---- tile loader: 1024 chunks (16B) each for A and B per stage
    auto load_tile = [&](int s, int k0) {
#pragma unroll
        for (int i = 0; i < 4; i++) {
            int ch = tid + (i << 8);          // 0..1023
            int r  = ch >> 3;                 // row 0..127
            int c  = ch & 7;                  // chunk 0..7
            uint32_t off = (uint32_t)(r * 128 + ((c ^ (r & 7)) << 4));
            cp16(sA0 + s * STAGE_BYTES + off, A    + (size_t)(bm + r) * K + k0 + (c << 2));
            cp16(sB0 + s * STAGE_BYTES + off, Bmat + (size_t)(bn + r) * K + k0 + (c << 2));
        }
    };

    // prologue: stages 0,1
    load_tile(0, 0);
    asm volatile("cp.async.commit_group;" ::: "memory");
    load_tile(1, 32);
    asm volatile("cp.async.commit_group;" ::: "memory");

    const int rb = (lane & 7) + ((lane >> 3) & 1) * 8;  // row-within-16 for ldmatrix
    const int chi = lane >> 4;                          // chunk select hi/lo

    for (int kt = 0; kt < KT; kt++) {
        int s = kt % 3;
        asm volatile("cp.async.wait_group 1;" ::: "memory");
        __syncthreads();

        int kn = kt + 2;
        if (kn < KT) load_tile(kn % 3, kn * 32);
        asm volatile("cp.async.commit_group;" ::: "memory");

        uint32_t sa = sA0 + s * STAGE_BYTES;
        uint32_t sb = sB0 + s * STAGE_BYTES;
#pragma unroll
        for (int kk = 0; kk < 4; kk++) {
            uint32_t af[4][4];
#pragma unroll
            for (int mi = 0; mi < 4; mi++) {
                int r = wm + (mi << 4) + rb;
                int c = (kk << 1) + chi;
                LDSM4(af[mi][0], af[mi][1], af[mi][2], af[mi][3],
                      sa + r * 128 + ((c ^ (r & 7)) << 4));
            }
            uint32_t bf[2][4];
#pragma unroll
            for (int jj = 0; jj < 2; jj++) {
                int r = wn + (jj << 4) + rb;
                int c = (kk << 1) + chi;
                LDSM4(bf[jj][0], bf[jj][1], bf[jj][2], bf[jj][3],
                      sb + r * 128 + ((c ^ (r & 7)) << 4));
            }
#pragma unroll
            for (int mi = 0; mi < 4; mi++)
#pragma unroll
                for (int nj = 0; nj < 4; nj++)
                    MMA_TF32(acc[mi][nj], af[mi],
                             bf[nj >> 1][nj & 1], bf[nj >> 1][2 + (nj & 1)]);
        }
    }

    // ---- epilogue
    const int gid = lane >> 2, tig = lane & 3;
#pragma unroll
    for (int nj = 0; nj < 4; nj++) {
        int n0 = bn + wn + (nj << 3) + (tig << 1);
        if (MODE == 1) {
            float g0 = g_gam2[n0], g1 = g_gam2[n0 + 1];
            float q0 = g_bg[n0],   q1 = g_bg[n0 + 1];
#pragma unroll
            for (int mi = 0; mi < 4; mi++) {
                int m0 = bm + wm + (mi << 4) + gid;
                float2 v0 = make_float2(fmaf(acc[mi][nj][0], g0, q0),
                                        fmaf(acc[mi][nj][1], g1, q1));
                float2 v1 = make_float2(fmaf(acc[mi][nj][2], g0, q0),
                                        fmaf(acc[mi][nj][3], g1, q1));
                *reinterpret_cast<float2*>(&g_H[(size_t)m0 * NTOT + n0]) = v0;
                *reinterpret_cast<float2*>(&g_H[(size_t)(m0 + 8) * NTOT + n0]) = v1;
            }
        } else {
            float b0 = bias[n0], b1 = bias[n0 + 1];
#pragma unroll
            for (int mi = 0; mi < 4; mi++) {
                int m0 = bm + wm + (mi << 4) + gid;
                float2 x0 = *reinterpret_cast<const float2*>(&resid[(size_t)m0 * DM + n0]);
                float2 x1 = *reinterpret_cast<const float2*>(&resid[(size_t)(m0 + 8) * DM + n0]);
                float2 v0 = make_float2(acc[mi][nj][0] + b0 + x0.x,
                                        acc[mi][nj][1] + b1 + x0.y);
                float2 v1 = make_float2(acc[mi][nj][2] + b0 + x1.x,
                                        acc[mi][nj][3] + b1 + x1.y);
                *reinterpret_cast<float2*>(&g_y[(size_t)m0 * DM + n0]) = v0;
                *reinterpret_cast<float2*>(&g_y[(size_t)(m0 + 8) * DM + n0]) = v1;
            }
        }
    }
}

// ---------------------------------------------------------------------------
// Sequential LRU scan. Layout: g_H row m: re at col h, im at col 1024+h.
// Stores tf32-rounded outputs (all l, including l=0) so GEMM2 sees RTN tf32.
// ---------------------------------------------------------------------------
__global__ void scan_kernel(const float* __restrict__ mask) {
    int idx = blockIdx.x * blockDim.x + threadIdx.x;
    int b = idx >> 10;
    int h = idx & (HID - 1);
    const float lre = g_lre[h], lim = g_lim[h];
    const size_t base = (size_t)b * LSEQ * NTOT + h;
    float pre = 0.f, pim = 0.f;
    const int U = 8;
    float nre[U], nim[U];
#pragma unroll
    for (int j = 0; j < U; j++) {
        nre[j] = g_H[base + (size_t)j * NTOT];
        nim[j] = g_H[base + (size_t)j * NTOT + HID];
    }
    for (int l0 = 0; l0 < LSEQ; l0 += U) {
        float cre[U], cim[U];
#pragma unroll
        for (int j = 0; j < U; j++) { cre[j] = nre[j]; cim[j] = nim[j]; }
        if (l0 + U < LSEQ) {
#pragma unroll
            for (int j = 0; j < U; j++) {
                nre[j] = g_H[base + (size_t)(l0 + U + j) * NTOT];
                nim[j] = g_H[base + (size_t)(l0 + U + j) * NTOT + HID];
            }
        }
#pragma unroll
        for (int j = 0; j < U; j++) {
            int l = l0 + j;
            if (l > 0) {
                float m = mask[b * LSEQ + l - 1];
                float ar = lre * m, ai = lim * m;
                float r  = cre[j] + ar * pre - ai * pim;
                float im = cim[j] + ar * pim + ai * pre;
                pre = r; pim = im;
            } else {
                pre = cre[j]; pim = cim[j];
            }
            g_H[base + (size_t)l * NTOT]       = tf32r(pre);
            g_H[base + (size_t)l * NTOT + HID] = tf32r(pim);
        }
    }
}

// ---------------------------------------------------------------------------
// LayerNorm over D=512 per row; one warp per row.
// ---------------------------------------------------------------------------
__global__ void ln_kernel(const float* __restrict__ lnw, const float* __restrict__ lnb,
                          float* __restrict__ out) {
    int row = blockIdx.x * 8 + (threadIdx.x >> 5);
    int lane = threadIdx.x & 31;
    const float* yr = g_y + (size_t)row * DM;
    float v[16];
    float s = 0.f;
#pragma unroll
    for (int i = 0; i < 16; i++) { v[i] = yr[lane + 32 * i]; s += v[i]; }
#pragma unroll
    for (int o = 16; o > 0; o >>= 1) s += __shfl_xor_sync(0xffffffffu, s, o);
    float mean = s * (1.0f / DM);
    float q = 0.f;
#pragma unroll
    for (int i = 0; i < 16; i++) { float d = v[i] - mean; q = fmaf(d, d, q); }
#pragma unroll
    for (int o = 16; o > 0; o >>= 1) q += __shfl_xor_sync(0xffffffffu, q, o);
    float inv = rsqrtf(q * (1.0f / DM) + 1e-5f);
#pragma unroll
    for (int i = 0; i < 16; i++) {
        int c = lane + 32 * i;
        out[(size_t)row * DM + c] = (v[i] - mean) * inv * lnw[c] + lnb[c];
    }
}

// ---------------------------------------------------------------------------
extern "C" void kernel_launch(void* const* d_in, const int* in_sizes, int n_in,
                              void* d_out, int out_size) {
    const float* x    = (const float*)d_in[0];
    const float* mask = (const float*)d_in[1];
    const float* plog = (const float*)d_in[2];
    const float* Wre  = (const float*)d_in[3];
    const float* Wim  = (const float*)d_in[4];
    const float* bre  = (const float*)d_in[5];
    const float* bim  = (const float*)d_in[6];
    const float* Wor  = (const float*)d_in[7];
    const float* Woi  = (const float*)d_in[8];
    const float* bor  = (const float*)d_in[9];
    // d_in[10] = b_out_im (unused: only real part survives)
    const float* lnw  = (const float*)d_in[11];
    const float* lnb  = (const float*)d_in[12];
    float* out = (float*)d_out;

    const int smem_bytes = 6 * STAGE_BYTES;  // 98304
    cudaFuncSetAttribute(gemm_tf32<DM, 1>,
                         cudaFuncAttributeMaxDynamicSharedMemorySize, smem_bytes);
    cudaFuncSetAttribute(gemm_tf32<NTOT, 2>,
                         cudaFuncAttributeMaxDynamicSharedMemorySize, smem_bytes);

    precompute_kernel<<<1, HID>>>(plog, bre, bim);
    cvt_x_kernel <<<(NTOK * DM / 4) / 256, 256>>>(x);
    cvt_w1_kernel<<<(HID * DM / 4) / 256, 256>>>(Wre, Wim);
    cvt_wo_kernel<<<(DM * NTOT / 4) / 256, 256>>>(Wor, Woi);

    // GEMM1: h = (X @ [Wre;Wim]^T + b) * gamma  -> g_H
    gemm_tf32<DM, 1><<<dim3(NTOK / 128, NTOT / 128), 256, smem_bytes>>>(nullptr, nullptr);

    // scan (in place on g_H)
    scan_kernel<<<(BDIM * HID) / 64, 64>>>(mask);

    // GEMM2: y = [Hre,Him] @ [Wor,-Woi]^T + b_out_re + x  -> g_y
    gemm_tf32<NTOT, 2><<<dim3(NTOK / 128, DM / 128), 256, smem_bytes>>>(bor, x);

    ln_kernel<<<NTOK / 8, 256>>>(lnw, lnb, out);
}

// round 10
// speedup vs baseline: 3.8920x; 1.4781x over previous
#include <cuda_runtime.h>
#include <cuda_fp16.h>
#include <cstdint>

#define NTOK 16384
#define BDIM 8
#define LSEQ 2048
#define DM   512
#define HID  1024
#define NTOT 2048   // 2*HID

// ---------------------------------------------------------------------------
// Device-global scratch (allocation-free)
// Layouts:
//   g_Xh : [NTOK, DM]  fp16 (rounded X)
//   g_W1h: [NTOT, DM]  fp16, rows interleaved: row 2h = Wre[h], row 2h+1 = Wim[h]
//   g_Woh: [DM, NTOT]  fp16, cols interleaved: col 2h = Wor[:,h], col 2h+1 = -Woi[:,h]
//   g_Hh : [NTOK, NTOT] fp16, cols interleaved: col 2h = re_h, col 2h+1 = im_h
// ---------------------------------------------------------------------------
__device__ __half g_Xh [(size_t)NTOK * DM];
__device__ __half g_W1h[(size_t)NTOT * DM];
__device__ __half g_Woh[(size_t)DM * NTOT];
__device__ __half g_Hh [(size_t)NTOK * NTOT];
__device__ float  g_y  [(size_t)NTOK * DM];
__device__ float  g_lre[HID], g_lim[HID];
__device__ float  g_gamI[NTOT], g_bgI[NTOT];   // interleaved gamma / bias*gamma

// ---------------------------------------------------------------------------
__global__ void precompute_kernel(const float* __restrict__ plog,
                                  const float* __restrict__ bre,
                                  const float* __restrict__ bim) {
    int h = threadIdx.x;  // 1024
    float nu = expf(plog[h]);
    float th = expf(plog[HID + h]);
    float ga = expf(plog[2 * HID + h]);
    float er = expf(-nu);
    g_lre[h] = er * cosf(th);
    g_lim[h] = er * sinf(th);
    g_gamI[2 * h] = ga;  g_gamI[2 * h + 1] = ga;
    g_bgI[2 * h] = bre[h] * ga;  g_bgI[2 * h + 1] = bim[h] * ga;
}

// ---------------------------------------------------------------------------
// fp16 conversion pre-passes
// ---------------------------------------------------------------------------
__global__ void cvt_x_kernel(const float* __restrict__ x) {
    int i = blockIdx.x * 256 + threadIdx.x;        // NTOK*DM/4 threads
    float4 v = reinterpret_cast<const float4*>(x)[i];
    __half2* out = reinterpret_cast<__half2*>(g_Xh) + 2 * i;
    out[0] = __floats2half2_rn(v.x, v.y);
    out[1] = __floats2half2_rn(v.z, v.w);
}

// W1 rows interleaved: out row 2h = Wre[h], row 2h+1 = Wim[h]
__global__ void cvt_w1_kernel(const float* __restrict__ Wre, const float* __restrict__ Wim) {
    int i = blockIdx.x * 256 + threadIdx.x;        // HID*DM/4 threads
    int h  = i >> 7;                                // DM/4 = 128 float4 per row
    int kq = i & 127;
    float4 a = reinterpret_cast<const float4*>(Wre)[i];
    float4 b = reinterpret_cast<const float4*>(Wim)[i];
    __half2* outA = reinterpret_cast<__half2*>(g_W1h + (size_t)(2 * h) * DM + 4 * kq);
    __half2* outB = reinterpret_cast<__half2*>(g_W1h + (size_t)(2 * h + 1) * DM + 4 * kq);
    outA[0] = __floats2half2_rn(a.x, a.y);
    outA[1] = __floats2half2_rn(a.z, a.w);
    outB[0] = __floats2half2_rn(b.x, b.y);
    outB[1] = __floats2half2_rn(b.z, b.w);
}

// Wo cols interleaved: out[d][2h] = Wor[d][h], out[d][2h+1] = -Woi[d][h]
__global__ void cvt_wo_kernel(const float* __restrict__ Wor, const float* __restrict__ Woi) {
    int i = blockIdx.x * 256 + threadIdx.x;        // DM*HID/4 threads
    int d  = i >> 8;                                // HID/4 = 256 float4 per row
    int hq = i & 255;                               // h = 4*hq .. 4*hq+3
    float4 a = reinterpret_cast<const float4*>(Wor)[i];
    float4 b = reinterpret_cast<const float4*>(Woi)[i];
    __half2* out = reinterpret_cast<__half2*>(g_Woh + (size_t)d * NTOT + 8 * hq);
    out[0] = __floats2half2_rn(a.x, -b.x);
    out[1] = __floats2half2_rn(a.y, -b.y);
    out[2] = __floats2half2_rn(a.z, -b.z);
    out[3] = __floats2half2_rn(a.w, -b.w);
}

// ---------------------------------------------------------------------------
// fp16 tensor-core GEMM: C[m][n] = sum_k A[m][k]*B[n][k]
// Block tile 128x128, BK=64 (fp16 rows = 128B), 3-stage cp.async, 2x4 warps
// of 64x32, mma.m16n8k16.
// MODE 1: A=g_Xh, B=g_W1h -> g_Hh (fp16) fused (acc*gamma + bias*gamma)
// MODE 2: A=g_Hh, B=g_Woh -> g_y (fp32) fused (+bias +residual)
// ---------------------------------------------------------------------------
#define STAGE_BYTES 16384   // per operand per stage: 128 rows * 128B

__device__ __forceinline__ void cp16(uint32_t dst, const __half* src) {
    asm volatile("cp.async.cg.shared.global [%0], [%1], 16;" :: "r"(dst), "l"(src));
}

#define LDSM4(R0, R1, R2, R3, addr) \
    asm volatile("ldmatrix.sync.aligned.m8n8.x4.shared.b16 {%0,%1,%2,%3}, [%4];" \
                 : "=r"(R0), "=r"(R1), "=r"(R2), "=r"(R3) : "r"(addr))

#define MMA_F16(c, a, b0r, b1r) \
    asm volatile("mma.sync.aligned.m16n8k16.row.col.f32.f16.f16.f32 " \
                 "{%0,%1,%2,%3}, {%4,%5,%6,%7}, {%8,%9}, {%0,%1,%2,%3};" \
                 : "+f"(c[0]), "+f"(c[1]), "+f"(c[2]), "+f"(c[3]) \
                 : "r"(a[0]), "r"(a[1]), "r"(a[2]), "r"(a[3]), "r"(b0r), "r"(b1r))

template<int K, int MODE>
__global__ __launch_bounds__(256, 2)
void gemm_f16(const float* __restrict__ bias, const float* __restrict__ resid) {
    extern __shared__ char smem[];
    const __half* A    = (MODE == 1) ? g_Xh  : g_Hh;
    const __half* Bmat = (MODE == 1) ? g_W1h : g_Woh;

    const int tid  = threadIdx.x;
    const int lane = tid & 31;
    const int wid  = tid >> 5;
    const int wm   = (wid >> 2) * 64;   // warp m offset (0/64)
    const int wn   = (wid & 3) * 32;    // warp n offset (0/32/64/96)
    const int bm   = blockIdx.x * 128;
    const int bn   = blockIdx.y * 128;

    uint32_t sm_base = (uint32_t)__cvta_generic_to_shared(smem);
    uint32_t sA0 = sm_base;
    uint32_t sB0 = sm_base + 3 * STAGE_BYTES;

    float acc[4][4][4];
#pragma unroll
    for (int i = 0; i < 4; i++)
#pragma unroll
        for (int j = 0; j < 4; j++)
#pragma unroll
            for (int e = 0; e < 4; e++) acc[i][j][e] = 0.f;

    constexpr int KT = K / 64;

    // ---- tile loader: 1024 16B chunks each for A and B per stage
    auto load_tile = [&](int s, int k0) {
#pragma unroll
        for (int i = 0; i < 4; i++) {
            int ch = tid + (i << 8);          // 0..1023
            int r  = ch >> 3;                 // row 0..127
            int c  = ch & 7;                  // 16B chunk 0..7 (8 fp16 each)
            uint32_t off = (uint32_t)(r * 128 + ((c ^ (r & 7)) << 4));
            cp16(sA0 + s * STAGE_BYTES + off, A    + (size_t)(bm + r) * K + k0 + (c << 3));
            cp16(sB0 + s * STAGE_BYTES + off, Bmat + (size_t)(bn + r) * K + k0 + (c << 3));
        }
    };

    // prologue: stages 0,1
    load_tile(0, 0);
    asm volatile("cp.async.commit_group;" ::: "memory");
    load_tile(1, 64);
    asm volatile("cp.async.commit_group;" ::: "memory");

    const int rb  = (lane & 7) + ((lane >> 3) & 1) * 8;  // row-within-16 for ldmatrix
    const int chi = lane >> 4;                           // chunk hi/lo select

    for (int kt = 0; kt < KT; kt++) {
        int s = kt % 3;
        asm volatile("cp.async.wait_group 1;" ::: "memory");
        __syncthreads();

        int kn = kt + 2;
        if (kn < KT) load_tile(kn % 3, kn * 64);
        asm volatile("cp.async.commit_group;" ::: "memory");

        uint32_t sa = sA0 + s * STAGE_BYTES;
        uint32_t sb = sB0 + s * STAGE_BYTES;
#pragma unroll
        for (int kk = 0; kk < 4; kk++) {       // 4 x k16 per k64 stage
            uint32_t af[4][4];
#pragma unroll
            for (int mi = 0; mi < 4; mi++) {
                int r = wm + (mi << 4) + rb;
                int c = (kk << 1) + chi;
                LDSM4(af[mi][0], af[mi][1], af[mi][2], af[mi][3],
                      sa + r * 128 + ((c ^ (r & 7)) << 4));
            }
            uint32_t bf[2][4];
#pragma unroll
            for (int jj = 0; jj < 2; jj++) {
                int r = wn + (jj << 4) + rb;
                int c = (kk << 1) + chi;
                LDSM4(bf[jj][0], bf[jj][1], bf[jj][2], bf[jj][3],
                      sb + r * 128 + ((c ^ (r & 7)) << 4));
            }
#pragma unroll
            for (int mi = 0; mi < 4; mi++)
#pragma unroll
                for (int nj = 0; nj < 4; nj++)
                    MMA_F16(acc[mi][nj], af[mi],
                            bf[nj >> 1][nj & 1], bf[nj >> 1][2 + (nj & 1)]);
        }
    }

    // ---- epilogue
    const int gid = lane >> 2, tig = lane & 3;
#pragma unroll
    for (int nj = 0; nj < 4; nj++) {
        int n0 = bn + wn + (nj << 3) + (tig << 1);
        if (MODE == 1) {
            float g0 = g_gamI[n0], g1 = g_gamI[n0 + 1];
            float q0 = g_bgI[n0],  q1 = g_bgI[n0 + 1];
#pragma unroll
            for (int mi = 0; mi < 4; mi++) {
                int m0 = bm + wm + (mi << 4) + gid;
                __half2 v0 = __floats2half2_rn(fmaf(acc[mi][nj][0], g0, q0),
                                               fmaf(acc[mi][nj][1], g1, q1));
                __half2 v1 = __floats2half2_rn(fmaf(acc[mi][nj][2], g0, q0),
                                               fmaf(acc[mi][nj][3], g1, q1));
                *reinterpret_cast<__half2*>(&g_Hh[(size_t)m0 * NTOT + n0]) = v0;
                *reinterpret_cast<__half2*>(&g_Hh[(size_t)(m0 + 8) * NTOT + n0]) = v1;
            }
        } else {
            float b0 = bias[n0], b1 = bias[n0 + 1];
#pragma unroll
            for (int mi = 0; mi < 4; mi++) {
                int m0 = bm + wm + (mi << 4) + gid;
                float2 x0 = *reinterpret_cast<const float2*>(&resid[(size_t)m0 * DM + n0]);
                float2 x1 = *reinterpret_cast<const float2*>(&resid[(size_t)(m0 + 8) * DM + n0]);
                float2 v0 = make_float2(acc[mi][nj][0] + b0 + x0.x,
                                        acc[mi][nj][1] + b1 + x0.y);
                float2 v1 = make_float2(acc[mi][nj][2] + b0 + x1.x,
                                        acc[mi][nj][3] + b1 + x1.y);
                *reinterpret_cast<float2*>(&g_y[(size_t)m0 * DM + n0]) = v0;
                *reinterpret_cast<float2*>(&g_y[(size_t)(m0 + 8) * DM + n0]) = v1;
            }
        }
    }
}

// ---------------------------------------------------------------------------
// Sequential LRU scan, in place on g_Hh (fp16, re/im interleaved -> __half2).
// Recurrence state kept in fp32 registers; stores RN-rounded fp16.
// ---------------------------------------------------------------------------
__global__ void scan_kernel(const float* __restrict__ mask) {
    int idx = blockIdx.x * blockDim.x + threadIdx.x;
    int b = idx >> 10;
    int h = idx & (HID - 1);
    const float lre = g_lre[h], lim = g_lim[h];
    __half2* p = reinterpret_cast<__half2*>(g_Hh + (size_t)b * LSEQ * NTOT + 2 * h);
    const int STRIDE = NTOT / 2;   // half2 stride per l
    float pre = 0.f, pim = 0.f;
    const int U = 8;
    float2 nv[U];
#pragma unroll
    for (int j = 0; j < U; j++) nv[j] = __half22float2(p[(size_t)j * STRIDE]);
    for (int l0 = 0; l0 < LSEQ; l0 += U) {
        float2 cv[U];
#pragma unroll
        for (int j = 0; j < U; j++) cv[j] = nv[j];
        if (l0 + U < LSEQ) {
#pragma unroll
            for (int j = 0; j < U; j++)
                nv[j] = __half22float2(p[(size_t)(l0 + U + j) * STRIDE]);
        }
#pragma unroll
        for (int j = 0; j < U; j++) {
            int l = l0 + j;
            if (l > 0) {
                float m = mask[b * LSEQ + l - 1];
                float ar = lre * m, ai = lim * m;
                float r  = cv[j].x + ar * pre - ai * pim;
                float im = cv[j].y + ar * pim + ai * pre;
                pre = r; pim = im;
                p[(size_t)l * STRIDE] = __floats2half2_rn(r, im);
            } else {
                pre = cv[j].x; pim = cv[j].y;
            }
        }
    }
}

// ---------------------------------------------------------------------------
__global__ void ln_kernel(const float* __restrict__ lnw, const float* __restrict__ lnb,
                          float* __restrict__ out) {
    int row = blockIdx.x * 8 + (threadIdx.x >> 5);
    int lane = threadIdx.x & 31;
    const float* yr = g_y + (size_t)row * DM;
    float v[16];
    float s = 0.f;
#pragma unroll
    for (int i = 0; i < 16; i++) { v[i] = yr[lane + 32 * i]; s += v[i]; }
#pragma unroll
    for (int o = 16; o > 0; o >>= 1) s += __shfl_xor_sync(0xffffffffu, s, o);
    float mean = s * (1.0f / DM);
    float q = 0.f;
#pragma unroll
    for (int i = 0; i < 16; i++) { float d = v[i] - mean; q = fmaf(d, d, q); }
#pragma unroll
    for (int o = 16; o > 0; o >>= 1) q += __shfl_xor_sync(0xffffffffu, q, o);
    float inv = rsqrtf(q * (1.0f / DM) + 1e-5f);
#pragma unroll
    for (int i = 0; i < 16; i++) {
        int c = lane + 32 * i;
        out[(size_t)row * DM + c] = (v[i] - mean) * inv * lnw[c] + lnb[c];
    }
}

// ---------------------------------------------------------------------------
extern "C" void kernel_launch(void* const* d_in, const int* in_sizes, int n_in,
                              void* d_out, int out_size) {
    const float* x    = (const float*)d_in[0];
    const float* mask = (const float*)d_in[1];
    const float* plog = (const float*)d_in[2];
    const float* Wre  = (const float*)d_in[3];
    const float* Wim  = (const float*)d_in[4];
    const float* bre  = (const float*)d_in[5];
    const float* bim  = (const float*)d_in[6];
    const float* Wor  = (const float*)d_in[7];
    const float* Woi  = (const float*)d_in[8];
    const float* bor  = (const float*)d_in[9];
    // d_in[10] = b_out_im (unused: only real part survives)
    const float* lnw  = (const float*)d_in[11];
    const float* lnb  = (const float*)d_in[12];
    float* out = (float*)d_out;

    const int smem_bytes = 6 * STAGE_BYTES;  // 98304
    cudaFuncSetAttribute(gemm_f16<DM, 1>,
                         cudaFuncAttributeMaxDynamicSharedMemorySize, smem_bytes);
    cudaFuncSetAttribute(gemm_f16<NTOT, 2>,
                         cudaFuncAttributeMaxDynamicSharedMemorySize, smem_bytes);

    precompute_kernel<<<1, HID>>>(plog, bre, bim);
    cvt_x_kernel <<<(NTOK * DM / 4) / 256, 256>>>(x);
    cvt_w1_kernel<<<(HID * DM / 4) / 256, 256>>>(Wre, Wim);
    cvt_wo_kernel<<<(DM * HID / 4) / 256, 256>>>(Wor, Woi);

    // GEMM1: h = (X @ [Wre/Wim interleaved]^T + b) * gamma  -> g_Hh (fp16)
    gemm_f16<DM, 1><<<dim3(NTOK / 128, NTOT / 128), 256, smem_bytes>>>(nullptr, nullptr);

    // scan (in place on g_Hh)
    scan_kernel<<<(BDIM * HID) / 128, 128>>>(mask);

    // GEMM2: y = H_interleaved @ [Wor,-Woi interleaved]^T + b_out_re + x  -> g_y
    gemm_f16<NTOT, 2><<<dim3(NTOK / 128, DM / 128), 256, smem_bytes>>>(bor, x);

    ln_kernel<<<NTOK / 8, 256>>>(lnw, lnb, out);
}

// round 11
// speedup vs baseline: 3.8934x; 1.0004x over previous
#include <cuda_runtime.h>
#include <cuda_fp16.h>
#include <cstdint>

#define NTOK 16384
#define BDIM 8
#define LSEQ 2048
#define DM   512
#define HID  1024
#define NTOT 2048   // 2*HID

// ---------------------------------------------------------------------------
// Device-global scratch (allocation-free)
// Layouts:
//   g_Xh : [NTOK, DM]  fp16 (rounded X)
//   g_W1h: [NTOT, DM]  fp16, rows interleaved: row 2h = Wre[h], row 2h+1 = Wim[h]
//   g_Woh: [DM, NTOT]  fp16, cols interleaved: col 2h = Wor[:,h], col 2h+1 = -Woi[:,h]
//   g_Hh : [NTOK, NTOT] fp16, cols interleaved: col 2h = re_h, col 2h+1 = im_h
// ---------------------------------------------------------------------------
__device__ __half g_Xh [(size_t)NTOK * DM];
__device__ __half g_W1h[(size_t)NTOT * DM];
__device__ __half g_Woh[(size_t)DM * NTOT];
__device__ __half g_Hh [(size_t)NTOK * NTOT];
__device__ float  g_y  [(size_t)NTOK * DM];
__device__ float  g_lre[HID], g_lim[HID];
__device__ float  g_gamI[NTOT], g_bgI[NTOT];   // interleaved gamma / bias*gamma

// ---------------------------------------------------------------------------
__global__ void precompute_kernel(const float* __restrict__ plog,
                                  const float* __restrict__ bre,
                                  const float* __restrict__ bim) {
    int h = threadIdx.x;  // 1024
    float nu = expf(plog[h]);
    float th = expf(plog[HID + h]);
    float ga = expf(plog[2 * HID + h]);
    float er = expf(-nu);
    g_lre[h] = er * cosf(th);
    g_lim[h] = er * sinf(th);
    g_gamI[2 * h] = ga;  g_gamI[2 * h + 1] = ga;
    g_bgI[2 * h] = bre[h] * ga;  g_bgI[2 * h + 1] = bim[h] * ga;
}

// ---------------------------------------------------------------------------
// fp16 conversion pre-passes
// ---------------------------------------------------------------------------
__global__ void cvt_x_kernel(const float* __restrict__ x) {
    int i = blockIdx.x * 256 + threadIdx.x;        // NTOK*DM/4 threads
    float4 v = reinterpret_cast<const float4*>(x)[i];
    __half2* out = reinterpret_cast<__half2*>(g_Xh) + 2 * i;
    out[0] = __floats2half2_rn(v.x, v.y);
    out[1] = __floats2half2_rn(v.z, v.w);
}

// W1 rows interleaved: out row 2h = Wre[h], row 2h+1 = Wim[h]
__global__ void cvt_w1_kernel(const float* __restrict__ Wre, const float* __restrict__ Wim) {
    int i = blockIdx.x * 256 + threadIdx.x;        // HID*DM/4 threads
    int h  = i >> 7;                                // DM/4 = 128 float4 per row
    int kq = i & 127;
    float4 a = reinterpret_cast<const float4*>(Wre)[i];
    float4 b = reinterpret_cast<const float4*>(Wim)[i];
    __half2* outA = reinterpret_cast<__half2*>(g_W1h + (size_t)(2 * h) * DM + 4 * kq);
    __half2* outB = reinterpret_cast<__half2*>(g_W1h + (size_t)(2 * h + 1) * DM + 4 * kq);
    outA[0] = __floats2half2_rn(a.x, a.y);
    outA[1] = __floats2half2_rn(a.z, a.w);
    outB[0] = __floats2half2_rn(b.x, b.y);
    outB[1] = __floats2half2_rn(b.z, b.w);
}

// Wo cols interleaved: out[d][2h] = Wor[d][h], out[d][2h+1] = -Woi[d][h]
__global__ void cvt_wo_kernel(const float* __restrict__ Wor, const float* __restrict__ Woi) {
    int i = blockIdx.x * 256 + threadIdx.x;        // DM*HID/4 threads
    int d  = i >> 8;                                // HID/4 = 256 float4 per row
    int hq = i & 255;                               // h = 4*hq .. 4*hq+3
    float4 a = reinterpret_cast<const float4*>(Wor)[i];
    float4 b = reinterpret_cast<const float4*>(Woi)[i];
    __half2* out = reinterpret_cast<__half2*>(g_Woh + (size_t)d * NTOT + 8 * hq);
    out[0] = __floats2half2_rn(a.x, -b.x);
    out[1] = __floats2half2_rn(a.y, -b.y);
    out[2] = __floats2half2_rn(a.z, -b.z);
    out[3] = __floats2half2_rn(a.w, -b.w);
}

// ---------------------------------------------------------------------------
// fp16 tensor-core GEMM: C[m][n] = sum_k A[m][k]*B[n][k]
// Block tile 128x128, BK=64, 3-stage cp.async, 4 warps (2x2) of 64x64 each,
// mma.m16n8k16. 128 threads, 2 CTAs/SM.
// MODE 1: A=g_Xh, B=g_W1h -> g_Hh (fp16) fused (acc*gamma + bias*gamma)
// MODE 2: A=g_Hh, B=g_Woh -> g_y (fp32) fused (+bias +residual)
// ---------------------------------------------------------------------------
#define STAGE_BYTES 16384   // per operand per stage: 128 rows * 128B

__device__ __forceinline__ void cp16(uint32_t dst, const __half* src) {
    asm volatile("cp.async.cg.shared.global [%0], [%1], 16;" :: "r"(dst), "l"(src));
}

#define LDSM4(R0, R1, R2, R3, addr) \
    asm volatile("ldmatrix.sync.aligned.m8n8.x4.shared.b16 {%0,%1,%2,%3}, [%4];" \
                 : "=r"(R0), "=r"(R1), "=r"(R2), "=r"(R3) : "r"(addr))

#define MMA_F16(c, a, b0r, b1r) \
    asm volatile("mma.sync.aligned.m16n8k16.row.col.f32.f16.f16.f32 " \
                 "{%0,%1,%2,%3}, {%4,%5,%6,%7}, {%8,%9}, {%0,%1,%2,%3};" \
                 : "+f"(c[0]), "+f"(c[1]), "+f"(c[2]), "+f"(c[3]) \
                 : "r"(a[0]), "r"(a[1]), "r"(a[2]), "r"(a[3]), "r"(b0r), "r"(b1r))

template<int K, int MODE>
__global__ __launch_bounds__(128, 2)
void gemm_f16(const float* __restrict__ bias, const float* __restrict__ resid) {
    extern __shared__ char smem[];
    const __half* A    = (MODE == 1) ? g_Xh  : g_Hh;
    const __half* Bmat = (MODE == 1) ? g_W1h : g_Woh;

    const int tid  = threadIdx.x;
    const int lane = tid & 31;
    const int wid  = tid >> 5;          // 0..3
    const int wm   = (wid >> 1) * 64;   // warp m offset (0/64)
    const int wn   = (wid & 1) * 64;    // warp n offset (0/64)
    const int bm   = blockIdx.x * 128;
    const int bn   = blockIdx.y * 128;

    uint32_t sm_base = (uint32_t)__cvta_generic_to_shared(smem);
    uint32_t sA0 = sm_base;
    uint32_t sB0 = sm_base + 3 * STAGE_BYTES;

    float acc[4][8][4];
#pragma unroll
    for (int i = 0; i < 4; i++)
#pragma unroll
        for (int j = 0; j < 8; j++)
#pragma unroll
            for (int e = 0; e < 4; e++) acc[i][j][e] = 0.f;

    constexpr int KT = K / 64;

    // ---- tile loader: 1024 16B chunks each for A and B per stage (128 thr)
    auto load_tile = [&](int s, int k0) {
#pragma unroll
        for (int i = 0; i < 8; i++) {
            int ch = tid + (i << 7);          // 0..1023
            int r  = ch >> 3;                 // row 0..127
            int c  = ch & 7;                  // 16B chunk 0..7 (8 fp16 each)
            uint32_t off = (uint32_t)(r * 128 + ((c ^ (r & 7)) << 4));
            cp16(sA0 + s * STAGE_BYTES + off, A    + (size_t)(bm + r) * K + k0 + (c << 3));
            cp16(sB0 + s * STAGE_BYTES + off, Bmat + (size_t)(bn + r) * K + k0 + (c << 3));
        }
    };

    // prologue: stages 0,1
    load_tile(0, 0);
    asm volatile("cp.async.commit_group;" ::: "memory");
    load_tile(1, 64);
    asm volatile("cp.async.commit_group;" ::: "memory");

    const int rb  = (lane & 7) + ((lane >> 3) & 1) * 8;  // row-within-16 for ldmatrix
    const int chi = lane >> 4;                           // chunk hi/lo select

    for (int kt = 0; kt < KT; kt++) {
        int s = kt % 3;
        asm volatile("cp.async.wait_group 1;" ::: "memory");
        __syncthreads();

        int kn = kt + 2;
        if (kn < KT) load_tile(kn % 3, kn * 64);
        asm volatile("cp.async.commit_group;" ::: "memory");

        uint32_t sa = sA0 + s * STAGE_BYTES;
        uint32_t sb = sB0 + s * STAGE_BYTES;
#pragma unroll
        for (int kk = 0; kk < 4; kk++) {       // 4 x k16 per k64 stage
            uint32_t af[4][4];
#pragma unroll
            for (int mi = 0; mi < 4; mi++) {
                int r = wm + (mi << 4) + rb;
                int c = (kk << 1) + chi;
                LDSM4(af[mi][0], af[mi][1], af[mi][2], af[mi][3],
                      sa + r * 128 + ((c ^ (r & 7)) << 4));
            }
            uint32_t bf[4][4];
#pragma unroll
            for (int jj = 0; jj < 4; jj++) {
                int r = wn + (jj << 4) + rb;
                int c = (kk << 1) + chi;
                LDSM4(bf[jj][0], bf[jj][1], bf[jj][2], bf[jj][3],
                      sb + r * 128 + ((c ^ (r & 7)) << 4));
            }
#pragma unroll
            for (int mi = 0; mi < 4; mi++)
#pragma unroll
                for (int nj = 0; nj < 8; nj++)
                    MMA_F16(acc[mi][nj], af[mi],
                            bf[nj >> 1][nj & 1], bf[nj >> 1][2 + (nj & 1)]);
        }
    }

    // ---- epilogue
    const int gid = lane >> 2, tig = lane & 3;
#pragma unroll
    for (int nj = 0; nj < 8; nj++) {
        int n0 = bn + wn + (nj << 3) + (tig << 1);
        if (MODE == 1) {
            float g0 = g_gamI[n0], g1 = g_gamI[n0 + 1];
            float q0 = g_bgI[n0],  q1 = g_bgI[n0 + 1];
#pragma unroll
            for (int mi = 0; mi < 4; mi++) {
                int m0 = bm + wm + (mi << 4) + gid;
                __half2 v0 = __floats2half2_rn(fmaf(acc[mi][nj][0], g0, q0),
                                               fmaf(acc[mi][nj][1], g1, q1));
                __half2 v1 = __floats2half2_rn(fmaf(acc[mi][nj][2], g0, q0),
                                               fmaf(acc[mi][nj][3], g1, q1));
                *reinterpret_cast<__half2*>(&g_Hh[(size_t)m0 * NTOT + n0]) = v0;
                *reinterpret_cast<__half2*>(&g_Hh[(size_t)(m0 + 8) * NTOT + n0]) = v1;
            }
        } else {
            float b0 = bias[n0], b1 = bias[n0 + 1];
#pragma unroll
            for (int mi = 0; mi < 4; mi++) {
                int m0 = bm + wm + (mi << 4) + gid;
                float2 x0 = *reinterpret_cast<const float2*>(&resid[(size_t)m0 * DM + n0]);
                float2 x1 = *reinterpret_cast<const float2*>(&resid[(size_t)(m0 + 8) * DM + n0]);
                float2 v0 = make_float2(acc[mi][nj][0] + b0 + x0.x,
                                        acc[mi][nj][1] + b1 + x0.y);
                float2 v1 = make_float2(acc[mi][nj][2] + b0 + x1.x,
                                        acc[mi][nj][3] + b1 + x1.y);
                *reinterpret_cast<float2*>(&g_y[(size_t)m0 * DM + n0]) = v0;
                *reinterpret_cast<float2*>(&g_y[(size_t)(m0 + 8) * DM + n0]) = v1;
            }
        }
    }
}

// ---------------------------------------------------------------------------
// Sequential LRU scan, in place on g_Hh (fp16, re/im interleaved -> __half2).
// Recurrence state kept in fp32 registers; stores RN-rounded fp16.
// ---------------------------------------------------------------------------
__global__ void scan_kernel(const float* __restrict__ mask) {
    int idx = blockIdx.x * blockDim.x + threadIdx.x;
    int b = idx >> 10;
    int h = idx & (HID - 1);
    const float lre = g_lre[h], lim = g_lim[h];
    __half2* p = reinterpret_cast<__half2*>(g_Hh + (size_t)b * LSEQ * NTOT + 2 * h);
    const int STRIDE = NTOT / 2;   // half2 stride per l
    float pre = 0.f, pim = 0.f;
    const int U = 8;
    float2 nv[U];
#pragma unroll
    for (int j = 0; j < U; j++) nv[j] = __half22float2(p[(size_t)j * STRIDE]);
    for (int l0 = 0; l0 < LSEQ; l0 += U) {
        float2 cv[U];
#pragma unroll
        for (int j = 0; j < U; j++) cv[j] = nv[j];
        if (l0 + U < LSEQ) {
#pragma unroll
            for (int j = 0; j < U; j++)
                nv[j] = __half22float2(p[(size_t)(l0 + U + j) * STRIDE]);
        }
#pragma unroll
        for (int j = 0; j < U; j++) {
            int l = l0 + j;
            if (l > 0) {
                float m = mask[b * LSEQ + l - 1];
                float ar = lre * m, ai = lim * m;
                float r  = cv[j].x + ar * pre - ai * pim;
                float im = cv[j].y + ar * pim + ai * pre;
                pre = r; pim = im;
                p[(size_t)l * STRIDE] = __floats2half2_rn(r, im);
            } else {
                pre = cv[j].x; pim = cv[j].y;
            }
        }
    }
}

// ---------------------------------------------------------------------------
__global__ void ln_kernel(const float* __restrict__ lnw, const float* __restrict__ lnb,
                          float* __restrict__ out) {
    int row = blockIdx.x * 8 + (threadIdx.x >> 5);
    int lane = threadIdx.x & 31;
    const float* yr = g_y + (size_t)row * DM;
    float v[16];
    float s = 0.f;
#pragma unroll
    for (int i = 0; i < 16; i++) { v[i] = yr[lane + 32 * i]; s += v[i]; }
#pragma unroll
    for (int o = 16; o > 0; o >>= 1) s += __shfl_xor_sync(0xffffffffu, s, o);
    float mean = s * (1.0f / DM);
    float q = 0.f;
#pragma unroll
    for (int i = 0; i < 16; i++) { float d = v[i] - mean; q = fmaf(d, d, q); }
#pragma unroll
    for (int o = 16; o > 0; o >>= 1) q += __shfl_xor_sync(0xffffffffu, q, o);
    float inv = rsqrtf(q * (1.0f / DM) + 1e-5f);
#pragma unroll
    for (int i = 0; i < 16; i++) {
        int c = lane + 32 * i;
        out[(size_t)row * DM + c] = (v[i] - mean) * inv * lnw[c] + lnb[c];
    }
}

// ---------------------------------------------------------------------------
extern "C" void kernel_launch(void* const* d_in, const int* in_sizes, int n_in,
                              void* d_out, int out_size) {
    const float* x    = (const float*)d_in[0];
    const float* mask = (const float*)d_in[1];
    const float* plog = (const float*)d_in[2];
    const float* Wre  = (const float*)d_in[3];
    const float* Wim  = (const float*)d_in[4];
    const float* bre  = (const float*)d_in[5];
    const float* bim  = (const float*)d_in[6];
    const float* Wor  = (const float*)d_in[7];
    const float* Woi  = (const float*)d_in[8];
    const float* bor  = (const float*)d_in[9];
    // d_in[10] = b_out_im (unused: only real part survives)
    const float* lnw  = (const float*)d_in[11];
    const float* lnb  = (const float*)d_in[12];
    float* out = (float*)d_out;

    const int smem_bytes = 6 * STAGE_BYTES;  // 98304
    cudaFuncSetAttribute(gemm_f16<DM, 1>,
                         cudaFuncAttributeMaxDynamicSharedMemorySize, smem_bytes);
    cudaFuncSetAttribute(gemm_f16<NTOT, 2>,
                         cudaFuncAttributeMaxDynamicSharedMemorySize, smem_bytes);

    precompute_kernel<<<1, HID>>>(plog, bre, bim);
    cvt_x_kernel <<<(NTOK * DM / 4) / 256, 256>>>(x);
    cvt_w1_kernel<<<(HID * DM / 4) / 256, 256>>>(Wre, Wim);
    cvt_wo_kernel<<<(DM * HID / 4) / 256, 256>>>(Wor, Woi);

    // GEMM1: h = (X @ [Wre/Wim interleaved]^T + b) * gamma  -> g_Hh (fp16)
    gemm_f16<DM, 1><<<dim3(NTOK / 128, NTOT / 128), 128, smem_bytes>>>(nullptr, nullptr);

    // scan (in place on g_Hh)
    scan_kernel<<<(BDIM * HID) / 128, 128>>>(mask);

    // GEMM2: y = H_interleaved @ [Wor,-Woi interleaved]^T + b_out_re + x  -> g_y
    gemm_f16<NTOT, 2><<<dim3(NTOK / 128, DM / 128), 128, smem_bytes>>>(bor, x);

    ln_kernel<<<NTOK / 8, 256>>>(lnw, lnb, out);
}

// round 12
// speedup vs baseline: 3.9505x; 1.0147x over previous
#include <cuda_runtime.h>
#include <cuda_fp16.h>
#include <cstdint>

#define NTOK 16384
#define BDIM 8
#define LSEQ 2048
#define DM   512
#define HID  1024
#define NTOT 2048   // 2*HID

// ---------------------------------------------------------------------------
// Device-global scratch (allocation-free)
// Layouts:
//   g_Xh : [NTOK, DM]  fp16 (rounded X)
//   g_W1h: [NTOT, DM]  fp16, rows interleaved: row 2h = Wre[h], row 2h+1 = Wim[h]
//   g_Woh: [DM, NTOT]  fp16, cols interleaved: col 2h = Wor[:,h], col 2h+1 = -Woi[:,h]
//   g_Hh : [NTOK, NTOT] fp16, cols interleaved: col 2h = re_h, col 2h+1 = im_h
// ---------------------------------------------------------------------------
__device__ __half g_Xh [(size_t)NTOK * DM];
__device__ __half g_W1h[(size_t)NTOT * DM];
__device__ __half g_Woh[(size_t)DM * NTOT];
__device__ __half g_Hh [(size_t)NTOK * NTOT];
__device__ float  g_y  [(size_t)NTOK * DM];
__device__ float  g_lre[HID], g_lim[HID];
__device__ float  g_gamI[NTOT], g_bgI[NTOT];   // interleaved gamma / bias*gamma

// ---------------------------------------------------------------------------
__global__ void precompute_kernel(const float* __restrict__ plog,
                                  const float* __restrict__ bre,
                                  const float* __restrict__ bim) {
    int h = threadIdx.x;  // 1024
    float nu = expf(plog[h]);
    float th = expf(plog[HID + h]);
    float ga = expf(plog[2 * HID + h]);
    float er = expf(-nu);
    g_lre[h] = er * cosf(th);
    g_lim[h] = er * sinf(th);
    g_gamI[2 * h] = ga;  g_gamI[2 * h + 1] = ga;
    g_bgI[2 * h] = bre[h] * ga;  g_bgI[2 * h + 1] = bim[h] * ga;
}

// ---------------------------------------------------------------------------
// fp16 conversion pre-passes
// ---------------------------------------------------------------------------
__global__ void cvt_x_kernel(const float* __restrict__ x) {
    int i = blockIdx.x * 256 + threadIdx.x;        // NTOK*DM/4 threads
    float4 v = reinterpret_cast<const float4*>(x)[i];
    __half2* out = reinterpret_cast<__half2*>(g_Xh) + 2 * i;
    out[0] = __floats2half2_rn(v.x, v.y);
    out[1] = __floats2half2_rn(v.z, v.w);
}

// Merged weight conversion.
// Blocks [0, 512): W1 rows interleaved (row 2h = Wre[h], row 2h+1 = Wim[h]).
// Blocks [512, 1024): Wo cols interleaved (col 2h = Wor[d][h], 2h+1 = -Woi[d][h]).
__global__ void cvt_w_kernel(const float* __restrict__ Wre, const float* __restrict__ Wim,
                             const float* __restrict__ Wor, const float* __restrict__ Woi) {
    if (blockIdx.x < 512) {
        int i = blockIdx.x * 256 + threadIdx.x;    // HID*DM/4 threads
        int h  = i >> 7;                            // DM/4 = 128 float4 per row
        int kq = i & 127;
        float4 a = reinterpret_cast<const float4*>(Wre)[i];
        float4 b = reinterpret_cast<const float4*>(Wim)[i];
        __half2* outA = reinterpret_cast<__half2*>(g_W1h + (size_t)(2 * h) * DM + 4 * kq);
        __half2* outB = reinterpret_cast<__half2*>(g_W1h + (size_t)(2 * h + 1) * DM + 4 * kq);
        outA[0] = __floats2half2_rn(a.x, a.y);
        outA[1] = __floats2half2_rn(a.z, a.w);
        outB[0] = __floats2half2_rn(b.x, b.y);
        outB[1] = __floats2half2_rn(b.z, b.w);
    } else {
        int i = (blockIdx.x - 512) * 256 + threadIdx.x;  // DM*HID/4 threads
        int d  = i >> 8;                            // HID/4 = 256 float4 per row
        int hq = i & 255;
        float4 a = reinterpret_cast<const float4*>(Wor)[i];
        float4 b = reinterpret_cast<const float4*>(Woi)[i];
        __half2* out = reinterpret_cast<__half2*>(g_Woh + (size_t)d * NTOT + 8 * hq);
        out[0] = __floats2half2_rn(a.x, -b.x);
        out[1] = __floats2half2_rn(a.y, -b.y);
        out[2] = __floats2half2_rn(a.z, -b.z);
        out[3] = __floats2half2_rn(a.w, -b.w);
    }
}

// ---------------------------------------------------------------------------
// fp16 tensor-core GEMM: C[m][n] = sum_k A[m][k]*B[n][k]
// Block tile TM x 128, BK=64, 3-stage cp.async, mma.m16n8k16, 128 threads.
// TM=128: 4 warps (2x2) of 64x64, 2 CTAs/SM.
// TM=64 : 4 warps (1x4) of 64x32, 3 CTAs/SM (finer grid for tail balance).
// MODE 1: A=g_Xh, B=g_W1h -> g_Hh (fp16) fused (acc*gamma + bias*gamma)
// MODE 2: A=g_Hh, B=g_Woh -> g_y (fp32) fused (+bias +residual)
// ---------------------------------------------------------------------------
__device__ __forceinline__ void cp16(uint32_t dst, const __half* src) {
    asm volatile("cp.async.cg.shared.global [%0], [%1], 16;" :: "r"(dst), "l"(src));
}

#define LDSM4(R0, R1, R2, R3, addr) \
    asm volatile("ldmatrix.sync.aligned.m8n8.x4.shared.b16 {%0,%1,%2,%3}, [%4];" \
                 : "=r"(R0), "=r"(R1), "=r"(R2), "=r"(R3) : "r"(addr))

#define MMA_F16(c, a, b0r, b1r) \
    asm volatile("mma.sync.aligned.m16n8k16.row.col.f32.f16.f16.f32 " \
                 "{%0,%1,%2,%3}, {%4,%5,%6,%7}, {%8,%9}, {%0,%1,%2,%3};" \
                 : "+f"(c[0]), "+f"(c[1]), "+f"(c[2]), "+f"(c[3]) \
                 : "r"(a[0]), "r"(a[1]), "r"(a[2]), "r"(a[3]), "r"(b0r), "r"(b1r))

template<int K, int MODE, int TM>
__global__ __launch_bounds__(128, (TM == 64) ? 3 : 2)
void gemm_f16(const float* __restrict__ bias, const float* __restrict__ resid) {
    extern __shared__ char smem[];
    const __half* A    = (MODE == 1) ? g_Xh  : g_Hh;
    const __half* Bmat = (MODE == 1) ? g_W1h : g_Woh;

    constexpr int ABYTES = TM * 128;      // A stage bytes
    constexpr int BBYTES = 16384;         // B stage bytes (128 rows x 128B)
    constexpr int NJ = (TM == 128) ? 8 : 4;  // 8-wide n groups per warp

    const int tid  = threadIdx.x;
    const int lane = tid & 31;
    const int wid  = tid >> 5;          // 0..3
    const int wm   = (TM == 128) ? (wid >> 1) * 64 : 0;
    const int wn   = (TM == 128) ? (wid & 1) * 64 : wid * 32;
    const int bm   = blockIdx.x * TM;
    const int bn   = blockIdx.y * 128;

    uint32_t sm_base = (uint32_t)__cvta_generic_to_shared(smem);
    uint32_t sA0 = sm_base;
    uint32_t sB0 = sm_base + 3 * ABYTES;

    float acc[4][NJ][4];
#pragma unroll
    for (int i = 0; i < 4; i++)
#pragma unroll
        for (int j = 0; j < NJ; j++)
#pragma unroll
            for (int e = 0; e < 4; e++) acc[i][j][e] = 0.f;

    constexpr int KT = K / 64;

    // ---- tile loader (128 threads): A = TM*8 chunks, B = 1024 chunks of 16B
    auto load_tile = [&](int s, int k0) {
#pragma unroll
        for (int i = 0; i < TM / 16; i++) {
            int ch = tid + (i << 7);
            int r  = ch >> 3;
            int c  = ch & 7;
            uint32_t off = (uint32_t)(r * 128 + ((c ^ (r & 7)) << 4));
            cp16(sA0 + s * ABYTES + off, A + (size_t)(bm + r) * K + k0 + (c << 3));
        }
#pragma unroll
        for (int i = 0; i < 8; i++) {
            int ch = tid + (i << 7);
            int r  = ch >> 3;
            int c  = ch & 7;
            uint32_t off = (uint32_t)(r * 128 + ((c ^ (r & 7)) << 4));
            cp16(sB0 + s * BBYTES + off, Bmat + (size_t)(bn + r) * K + k0 + (c << 3));
        }
    };

    // prologue: stages 0,1
    load_tile(0, 0);
    asm volatile("cp.async.commit_group;" ::: "memory");
    load_tile(1, 64);
    asm volatile("cp.async.commit_group;" ::: "memory");

    const int rb  = (lane & 7) + ((lane >> 3) & 1) * 8;  // row-within-16 for ldmatrix
    const int chi = lane >> 4;                           // chunk hi/lo select

    for (int kt = 0; kt < KT; kt++) {
        int s = kt % 3;
        asm volatile("cp.async.wait_group 1;" ::: "memory");
        __syncthreads();

        int kn = kt + 2;
        if (kn < KT) load_tile(kn % 3, kn * 64);
        asm volatile("cp.async.commit_group;" ::: "memory");

        uint32_t sa = sA0 + s * ABYTES;
        uint32_t sb = sB0 + s * BBYTES;
#pragma unroll
        for (int kk = 0; kk < 4; kk++) {       // 4 x k16 per k64 stage
            uint32_t af[4][4];
#pragma unroll
            for (int mi = 0; mi < 4; mi++) {
                int r = wm + (mi << 4) + rb;
                int c = (kk << 1) + chi;
                LDSM4(af[mi][0], af[mi][1], af[mi][2], af[mi][3],
                      sa + r * 128 + ((c ^ (r & 7)) << 4));
            }
            uint32_t bf[NJ / 2][4];
#pragma unroll
            for (int jj = 0; jj < NJ / 2; jj++) {
                int r = wn + (jj << 4) + rb;
                int c = (kk << 1) + chi;
                LDSM4(bf[jj][0], bf[jj][1], bf[jj][2], bf[jj][3],
                      sb + r * 128 + ((c ^ (r & 7)) << 4));
            }
#pragma unroll
            for (int mi = 0; mi < 4; mi++)
#pragma unroll
                for (int nj = 0; nj < NJ; nj++)
                    MMA_F16(acc[mi][nj], af[mi],
                            bf[nj >> 1][nj & 1], bf[nj >> 1][2 + (nj & 1)]);
        }
    }

    // ---- epilogue
    const int gid = lane >> 2, tig = lane & 3;
#pragma unroll
    for (int nj = 0; nj < NJ; nj++) {
        int n0 = bn + wn + (nj << 3) + (tig << 1);
        if (MODE == 1) {
            float g0 = g_gamI[n0], g1 = g_gamI[n0 + 1];
            float q0 = g_bgI[n0],  q1 = g_bgI[n0 + 1];
#pragma unroll
            for (int mi = 0; mi < 4; mi++) {
                int m0 = bm + wm + (mi << 4) + gid;
                __half2 v0 = __floats2half2_rn(fmaf(acc[mi][nj][0], g0, q0),
                                               fmaf(acc[mi][nj][1], g1, q1));
                __half2 v1 = __floats2half2_rn(fmaf(acc[mi][nj][2], g0, q0),
                                               fmaf(acc[mi][nj][3], g1, q1));
                *reinterpret_cast<__half2*>(&g_Hh[(size_t)m0 * NTOT + n0]) = v0;
                *reinterpret_cast<__half2*>(&g_Hh[(size_t)(m0 + 8) * NTOT + n0]) = v1;
            }
        } else {
            float b0 = bias[n0], b1 = bias[n0 + 1];
#pragma unroll
            for (int mi = 0; mi < 4; mi++) {
                int m0 = bm + wm + (mi << 4) + gid;
                float2 x0 = *reinterpret_cast<const float2*>(&resid[(size_t)m0 * DM + n0]);
                float2 x1 = *reinterpret_cast<const float2*>(&resid[(size_t)(m0 + 8) * DM + n0]);
                float2 v0 = make_float2(acc[mi][nj][0] + b0 + x0.x,
                                        acc[mi][nj][1] + b1 + x0.y);
                float2 v1 = make_float2(acc[mi][nj][2] + b0 + x1.x,
                                        acc[mi][nj][3] + b1 + x1.y);
                *reinterpret_cast<float2*>(&g_y[(size_t)m0 * DM + n0]) = v0;
                *reinterpret_cast<float2*>(&g_y[(size_t)(m0 + 8) * DM + n0]) = v1;
            }
        }
    }
}

// ---------------------------------------------------------------------------
// Sequential LRU scan, in place on g_Hh (fp16, re/im interleaved -> __half2).
// Recurrence state kept in fp32 registers; stores RN-rounded fp16.
// ---------------------------------------------------------------------------
__global__ void scan_kernel(const float* __restrict__ mask) {
    int idx = blockIdx.x * blockDim.x + threadIdx.x;
    int b = idx >> 10;
    int h = idx & (HID - 1);
    const float lre = g_lre[h], lim = g_lim[h];
    __half2* p = reinterpret_cast<__half2*>(g_Hh + (size_t)b * LSEQ * NTOT + 2 * h);
    const int STRIDE = NTOT / 2;   // half2 stride per l
    float pre = 0.f, pim = 0.f;
    const int U = 8;
    float2 nv[U];
#pragma unroll
    for (int j = 0; j < U; j++) nv[j] = __half22float2(p[(size_t)j * STRIDE]);
    for (int l0 = 0; l0 < LSEQ; l0 += U) {
        float2 cv[U];
#pragma unroll
        for (int j = 0; j < U; j++) cv[j] = nv[j];
        if (l0 + U < LSEQ) {
#pragma unroll
            for (int j = 0; j < U; j++)
                nv[j] = __half22float2(p[(size_t)(l0 + U + j) * STRIDE]);
        }
#pragma unroll
        for (int j = 0; j < U; j++) {
            int l = l0 + j;
            if (l > 0) {
                float m = mask[b * LSEQ + l - 1];
                float ar = lre * m, ai = lim * m;
                float r  = cv[j].x + ar * pre - ai * pim;
                float im = cv[j].y + ar * pim + ai * pre;
                pre = r; pim = im;
                p[(size_t)l * STRIDE] = __floats2half2_rn(r, im);
            } else {
                pre = cv[j].x; pim = cv[j].y;
            }
        }
    }
}

// ---------------------------------------------------------------------------
__global__ void ln_kernel(const float* __restrict__ lnw, const float* __restrict__ lnb,
                          float* __restrict__ out) {
    int row = blockIdx.x * 8 + (threadIdx.x >> 5);
    int lane = threadIdx.x & 31;
    const float* yr = g_y + (size_t)row * DM;
    float v[16];
    float s = 0.f;
#pragma unroll
    for (int i = 0; i < 16; i++) { v[i] = yr[lane + 32 * i]; s += v[i]; }
#pragma unroll
    for (int o = 16; o > 0; o >>= 1) s += __shfl_xor_sync(0xffffffffu, s, o);
    float mean = s * (1.0f / DM);
    float q = 0.f;
#pragma unroll
    for (int i = 0; i < 16; i++) { float d = v[i] - mean; q = fmaf(d, d, q); }
#pragma unroll
    for (int o = 16; o > 0; o >>= 1) q += __shfl_xor_sync(0xffffffffu, q, o);
    float inv = rsqrtf(q * (1.0f / DM) + 1e-5f);
#pragma unroll
    for (int i = 0; i < 16; i++) {
        int c = lane + 32 * i;
        out[(size_t)row * DM + c] = (v[i] - mean) * inv * lnw[c] + lnb[c];
    }
}

// ---------------------------------------------------------------------------
extern "C" void kernel_launch(void* const* d_in, const int* in_sizes, int n_in,
                              void* d_out, int out_size) {
    const float* x    = (const float*)d_in[0];
    const float* mask = (const float*)d_in[1];
    const float* plog = (const float*)d_in[2];
    const float* Wre  = (const float*)d_in[3];
    const float* Wim  = (const float*)d_in[4];
    const float* bre  = (const float*)d_in[5];
    const float* bim  = (const float*)d_in[6];
    const float* Wor  = (const float*)d_in[7];
    const float* Woi  = (const float*)d_in[8];
    const float* bor  = (const float*)d_in[9];
    // d_in[10] = b_out_im (unused: only real part survives)
    const float* lnw  = (const float*)d_in[11];
    const float* lnb  = (const float*)d_in[12];
    float* out = (float*)d_out;

    const int smem1 = 3 * (128 * 128 + 16384);  // 98304 (TM=128)
    const int smem2 = 3 * (64 * 128 + 16384);   // 73728 (TM=64)
    cudaFuncSetAttribute(gemm_f16<DM, 1, 128>,
                         cudaFuncAttributeMaxDynamicSharedMemorySize, smem1);
    cudaFuncSetAttribute(gemm_f16<NTOT, 2, 64>,
                         cudaFuncAttributeMaxDynamicSharedMemorySize, smem2);

    // Launch order chosen so gemm1 is the 4th launch (ncu capture slot).
    cvt_x_kernel <<<(NTOK * DM / 4) / 256, 256>>>(x);
    cvt_w_kernel <<<1024, 256>>>(Wre, Wim, Wor, Woi);
    precompute_kernel<<<1, HID>>>(plog, bre, bim);

    // GEMM1: h = (X @ [Wre/Wim interleaved]^T + b) * gamma  -> g_Hh (fp16)
    gemm_f16<DM, 1, 128><<<dim3(NTOK / 128, NTOT / 128), 128, smem1>>>(nullptr, nullptr);

    // scan (in place on g_Hh)
    scan_kernel<<<(BDIM * HID) / 128, 128>>>(mask);

    // GEMM2: y = H_interleaved @ [Wor,-Woi interleaved]^T + b_out_re + x  -> g_y
    gemm_f16<NTOT, 2, 64><<<dim3(NTOK / 64, DM / 128), 128, smem2>>>(bor, x);

    ln_kernel<<<NTOK / 8, 256>>>(lnw, lnb, out);
}

// round 13
// speedup vs baseline: 5.9538x; 1.5071x over previous
#include <cuda_runtime.h>
#include <cuda_fp16.h>
#include <cstdint>

#define NTOK 16384
#define BDIM 8
#define LSEQ 2048
#define DM   512
#define HID  1024
#define NTOT 2048   // 2*HID
#define NCH  16     // scan chunks per chain
#define CL   (LSEQ / NCH)   // 128

// ---------------------------------------------------------------------------
// Device-global scratch (allocation-free)
// ---------------------------------------------------------------------------
__device__ __half g_Xh [(size_t)NTOK * DM];
__device__ __half g_W1h[(size_t)NTOT * DM];
__device__ __half g_Woh[(size_t)DM * NTOT];
__device__ __half g_Hh [(size_t)NTOK * NTOT];
__device__ float  g_y  [(size_t)NTOK * DM];
__device__ float  g_lre[HID], g_lim[HID];
__device__ float  g_gamI[NTOT], g_bgI[NTOT];   // interleaved gamma / bias*gamma
__device__ float2 g_endl [BDIM * NCH * HID];   // chunk-local end state
__device__ float2 g_T    [BDIM * NCH * HID];   // chunk transfer coefficient
__device__ float2 g_carry[BDIM * NCH * HID];   // carry INTO each chunk

// ---------------------------------------------------------------------------
// fp16 conversion pre-passes
// ---------------------------------------------------------------------------
__global__ void cvt_x_kernel(const float* __restrict__ x) {
    int i = blockIdx.x * 256 + threadIdx.x;        // NTOK*DM/4 threads
    float4 v = reinterpret_cast<const float4*>(x)[i];
    __half2* out = reinterpret_cast<__half2*>(g_Xh) + 2 * i;
    out[0] = __floats2half2_rn(v.x, v.y);
    out[1] = __floats2half2_rn(v.z, v.w);
}

// Merged weight conversion + precompute.
// Blocks [0,512): W1 rows interleaved. [512,1024): Wo cols interleaved.
// Block 1024: lambda/gamma precompute.
__global__ void cvt_wp_kernel(const float* __restrict__ Wre, const float* __restrict__ Wim,
                              const float* __restrict__ Wor, const float* __restrict__ Woi,
                              const float* __restrict__ plog,
                              const float* __restrict__ bre, const float* __restrict__ bim) {
    if (blockIdx.x < 512) {
        int i = blockIdx.x * 256 + threadIdx.x;    // HID*DM/4 threads
        int h  = i >> 7;                            // DM/4 = 128 float4 per row
        int kq = i & 127;
        float4 a = reinterpret_cast<const float4*>(Wre)[i];
        float4 b = reinterpret_cast<const float4*>(Wim)[i];
        __half2* outA = reinterpret_cast<__half2*>(g_W1h + (size_t)(2 * h) * DM + 4 * kq);
        __half2* outB = reinterpret_cast<__half2*>(g_W1h + (size_t)(2 * h + 1) * DM + 4 * kq);
        outA[0] = __floats2half2_rn(a.x, a.y);
        outA[1] = __floats2half2_rn(a.z, a.w);
        outB[0] = __floats2half2_rn(b.x, b.y);
        outB[1] = __floats2half2_rn(b.z, b.w);
    } else if (blockIdx.x < 1024) {
        int i = (blockIdx.x - 512) * 256 + threadIdx.x;  // DM*HID/4 threads
        int d  = i >> 8;                            // HID/4 = 256 float4 per row
        int hq = i & 255;
        float4 a = reinterpret_cast<const float4*>(Wor)[i];
        float4 b = reinterpret_cast<const float4*>(Woi)[i];
        __half2* out = reinterpret_cast<__half2*>(g_Woh + (size_t)d * NTOT + 8 * hq);
        out[0] = __floats2half2_rn(a.x, -b.x);
        out[1] = __floats2half2_rn(a.y, -b.y);
        out[2] = __floats2half2_rn(a.z, -b.z);
        out[3] = __floats2half2_rn(a.w, -b.w);
    } else {
#pragma unroll
        for (int i = 0; i < 4; i++) {
            int h = threadIdx.x + 256 * i;
            float nu = expf(plog[h]);
            float th = expf(plog[HID + h]);
            float ga = expf(plog[2 * HID + h]);
            float er = expf(-nu);
            g_lre[h] = er * cosf(th);
            g_lim[h] = er * sinf(th);
            g_gamI[2 * h] = ga;  g_gamI[2 * h + 1] = ga;
            g_bgI[2 * h] = bre[h] * ga;  g_bgI[2 * h + 1] = bim[h] * ga;
        }
    }
}

// ---------------------------------------------------------------------------
// fp16 tensor-core GEMM: C[m][n] = sum_k A[m][k]*B[n][k]
// Block tile TM x 128, BK=64, 3-stage cp.async, mma.m16n8k16, 128 threads.
// MODE 1: A=g_Xh, B=g_W1h -> g_Hh (fp16) fused (acc*gamma + bias*gamma)
// MODE 2: A=g_Hh, B=g_Woh -> g_y (fp32) fused (+bias +residual)
// ---------------------------------------------------------------------------
__device__ __forceinline__ void cp16(uint32_t dst, const __half* src) {
    asm volatile("cp.async.cg.shared.global [%0], [%1], 16;" :: "r"(dst), "l"(src));
}

#define LDSM4(R0, R1, R2, R3, addr) \
    asm volatile("ldmatrix.sync.aligned.m8n8.x4.shared.b16 {%0,%1,%2,%3}, [%4];" \
                 : "=r"(R0), "=r"(R1), "=r"(R2), "=r"(R3) : "r"(addr))

#define MMA_F16(c, a, b0r, b1r) \
    asm volatile("mma.sync.aligned.m16n8k16.row.col.f32.f16.f16.f32 " \
                 "{%0,%1,%2,%3}, {%4,%5,%6,%7}, {%8,%9}, {%0,%1,%2,%3};" \
                 : "+f"(c[0]), "+f"(c[1]), "+f"(c[2]), "+f"(c[3]) \
                 : "r"(a[0]), "r"(a[1]), "r"(a[2]), "r"(a[3]), "r"(b0r), "r"(b1r))

template<int K, int MODE, int TM>
__global__ __launch_bounds__(128, (TM == 64) ? 3 : 2)
void gemm_f16(const float* __restrict__ bias, const float* __restrict__ resid) {
    extern __shared__ char smem[];
    const __half* A    = (MODE == 1) ? g_Xh  : g_Hh;
    const __half* Bmat = (MODE == 1) ? g_W1h : g_Woh;

    constexpr int ABYTES = TM * 128;
    constexpr int BBYTES = 16384;
    constexpr int NJ = (TM == 128) ? 8 : 4;

    const int tid  = threadIdx.x;
    const int lane = tid & 31;
    const int wid  = tid >> 5;
    const int wm   = (TM == 128) ? (wid >> 1) * 64 : 0;
    const int wn   = (TM == 128) ? (wid & 1) * 64 : wid * 32;
    const int bm   = blockIdx.x * TM;
    const int bn   = blockIdx.y * 128;

    uint32_t sm_base = (uint32_t)__cvta_generic_to_shared(smem);
    uint32_t sA0 = sm_base;
    uint32_t sB0 = sm_base + 3 * ABYTES;

    float acc[4][NJ][4];
#pragma unroll
    for (int i = 0; i < 4; i++)
#pragma unroll
        for (int j = 0; j < NJ; j++)
#pragma unroll
            for (int e = 0; e < 4; e++) acc[i][j][e] = 0.f;

    constexpr int KT = K / 64;

    auto load_tile = [&](int s, int k0) {
#pragma unroll
        for (int i = 0; i < TM / 16; i++) {
            int ch = tid + (i << 7);
            int r  = ch >> 3;
            int c  = ch & 7;
            uint32_t off = (uint32_t)(r * 128 + ((c ^ (r & 7)) << 4));
            cp16(sA0 + s * ABYTES + off, A + (size_t)(bm + r) * K + k0 + (c << 3));
        }
#pragma unroll
        for (int i = 0; i < 8; i++) {
            int ch = tid + (i << 7);
            int r  = ch >> 3;
            int c  = ch & 7;
            uint32_t off = (uint32_t)(r * 128 + ((c ^ (r & 7)) << 4));
            cp16(sB0 + s * BBYTES + off, Bmat + (size_t)(bn + r) * K + k0 + (c << 3));
        }
    };

    load_tile(0, 0);
    asm volatile("cp.async.commit_group;" ::: "memory");
    load_tile(1, 64);
    asm volatile("cp.async.commit_group;" ::: "memory");

    const int rb  = (lane & 7) + ((lane >> 3) & 1) * 8;
    const int chi = lane >> 4;

    for (int kt = 0; kt < KT; kt++) {
        int s = kt % 3;
        asm volatile("cp.async.wait_group 1;" ::: "memory");
        __syncthreads();

        int kn = kt + 2;
        if (kn < KT) load_tile(kn % 3, kn * 64);
        asm volatile("cp.async.commit_group;" ::: "memory");

        uint32_t sa = sA0 + s * ABYTES;
        uint32_t sb = sB0 + s * BBYTES;
#pragma unroll
        for (int kk = 0; kk < 4; kk++) {
            uint32_t af[4][4];
#pragma unroll
            for (int mi = 0; mi < 4; mi++) {
                int r = wm + (mi << 4) + rb;
                int c = (kk << 1) + chi;
                LDSM4(af[mi][0], af[mi][1], af[mi][2], af[mi][3],
                      sa + r * 128 + ((c ^ (r & 7)) << 4));
            }
            uint32_t bf[NJ / 2][4];
#pragma unroll
            for (int jj = 0; jj < NJ / 2; jj++) {
                int r = wn + (jj << 4) + rb;
                int c = (kk << 1) + chi;
                LDSM4(bf[jj][0], bf[jj][1], bf[jj][2], bf[jj][3],
                      sb + r * 128 + ((c ^ (r & 7)) << 4));
            }
#pragma unroll
            for (int mi = 0; mi < 4; mi++)
#pragma unroll
                for (int nj = 0; nj < NJ; nj++)
                    MMA_F16(acc[mi][nj], af[mi],
                            bf[nj >> 1][nj & 1], bf[nj >> 1][2 + (nj & 1)]);
        }
    }

    const int gid = lane >> 2, tig = lane & 3;
#pragma unroll
    for (int nj = 0; nj < NJ; nj++) {
        int n0 = bn + wn + (nj << 3) + (tig << 1);
        if (MODE == 1) {
            float g0 = g_gamI[n0], g1 = g_gamI[n0 + 1];
            float q0 = g_bgI[n0],  q1 = g_bgI[n0 + 1];
#pragma unroll
            for (int mi = 0; mi < 4; mi++) {
                int m0 = bm + wm + (mi << 4) + gid;
                __half2 v0 = __floats2half2_rn(fmaf(acc[mi][nj][0], g0, q0),
                                               fmaf(acc[mi][nj][1], g1, q1));
                __half2 v1 = __floats2half2_rn(fmaf(acc[mi][nj][2], g0, q0),
                                               fmaf(acc[mi][nj][3], g1, q1));
                *reinterpret_cast<__half2*>(&g_Hh[(size_t)m0 * NTOT + n0]) = v0;
                *reinterpret_cast<__half2*>(&g_Hh[(size_t)(m0 + 8) * NTOT + n0]) = v1;
            }
        } else {
            float b0 = bias[n0], b1 = bias[n0 + 1];
#pragma unroll
            for (int mi = 0; mi < 4; mi++) {
                int m0 = bm + wm + (mi << 4) + gid;
                float2 x0 = *reinterpret_cast<const float2*>(&resid[(size_t)m0 * DM + n0]);
                float2 x1 = *reinterpret_cast<const float2*>(&resid[(size_t)(m0 + 8) * DM + n0]);
                float2 v0 = make_float2(acc[mi][nj][0] + b0 + x0.x,
                                        acc[mi][nj][1] + b1 + x0.y);
                float2 v1 = make_float2(acc[mi][nj][2] + b0 + x1.x,
                                        acc[mi][nj][3] + b1 + x1.y);
                *reinterpret_cast<float2*>(&g_y[(size_t)m0 * DM + n0]) = v0;
                *reinterpret_cast<float2*>(&g_y[(size_t)(m0 + 8) * DM + n0]) = v1;
            }
        }
    }
}

// ---------------------------------------------------------------------------
// Chunked parallel LRU scan over g_Hh (fp16, re/im interleaved).
// h[l] = u[l] + f(l)*h[l-1],  f(l) = lambda * mask[l-1].
// By linearity: within chunk [l0, l0+CL): h[l] = hloc[l] + (prod f)*carry_in.
// Phase 1: per-chunk local end state + transfer coefficient T (reads u only).
// Combine : sequential carry propagation across NCH chunks per chain.
// Phase 2: re-scan each chunk from its carry_in, writing final h.
// Block = 128 threads = 128 h-channels of one (b, chunk); mask tile in smem.
// ---------------------------------------------------------------------------
template<int PHASE>
__global__ void scan_phase(const float* __restrict__ mask) {
    __shared__ float ms[CL];
    const int bid = blockIdx.x;          // b * NCH * 8 + c * 8 + hb
    const int b  = bid >> 7;
    const int c  = (bid >> 3) & (NCH - 1);
    const int hb = bid & 7;
    const int h  = hb * 128 + threadIdx.x;
    const int l0 = c * CL;

    {
        int gl = l0 + threadIdx.x - 1;
        ms[threadIdx.x] = (gl >= 0) ? mask[b * LSEQ + gl] : 0.f;
    }
    __syncthreads();

    const float lre = g_lre[h], lim = g_lim[h];
    __half2* p = reinterpret_cast<__half2*>(g_Hh)
               + (size_t)b * LSEQ * (NTOT / 2) + (size_t)l0 * (NTOT / 2) + h;
    const int S = NTOT / 2;

    float2 prev, T;
    if (PHASE == 1) { prev = make_float2(0.f, 0.f); T = make_float2(1.f, 0.f); }
    else            { prev = g_carry[(b * NCH + c) * HID + h]; }

    const int U = 8;
    float2 nv[U];
#pragma unroll
    for (int j = 0; j < U; j++) nv[j] = __half22float2(p[(size_t)j * S]);

    for (int j0 = 0; j0 < CL; j0 += U) {
        float2 cv[U];
#pragma unroll
        for (int j = 0; j < U; j++) cv[j] = nv[j];
        if (j0 + U < CL) {
#pragma unroll
            for (int j = 0; j < U; j++)
                nv[j] = __half22float2(p[(size_t)(j0 + U + j) * S]);
        }
#pragma unroll
        for (int j = 0; j < U; j++) {
            int l = l0 + j0 + j;
            if (l > 0) {
                float m = ms[j0 + j];
                float fr = lre * m, fi = lim * m;
                float r  = cv[j].x + fr * prev.x - fi * prev.y;
                float im = cv[j].y + fr * prev.y + fi * prev.x;
                prev.x = r; prev.y = im;
                if (PHASE == 1) {
                    float tr = fr * T.x - fi * T.y;
                    float ti = fr * T.y + fi * T.x;
                    T.x = tr; T.y = ti;
                }
            } else {
                prev = cv[j];
            }
            if (PHASE == 2) p[(size_t)(j0 + j) * S] = __floats2half2_rn(prev.x, prev.y);
        }
    }

    if (PHASE == 1) {
        int o = (b * NCH + c) * HID + h;
        g_endl[o] = prev;
        g_T[o]    = T;
    }
}

// Sequential carry propagation: 8192 threads, NCH steps each.
__global__ void scan_combine() {
    int idx = blockIdx.x * blockDim.x + threadIdx.x;
    int b = idx >> 10;
    int h = idx & (HID - 1);
    float2 carry = make_float2(0.f, 0.f);
#pragma unroll
    for (int c = 0; c < NCH; c++) {
        int o = (b * NCH + c) * HID + h;
        g_carry[o] = carry;
        float2 e = g_endl[o];
        float2 t = g_T[o];
        float r  = e.x + t.x * carry.x - t.y * carry.y;
        float im = e.y + t.x * carry.y + t.y * carry.x;
        carry.x = r; carry.y = im;
    }
}

// ---------------------------------------------------------------------------
__global__ void ln_kernel(const float* __restrict__ lnw, const float* __restrict__ lnb,
                          float* __restrict__ out) {
    int row = blockIdx.x * 8 + (threadIdx.x >> 5);
    int lane = threadIdx.x & 31;
    const float* yr = g_y + (size_t)row * DM;
    float v[16];
    float s = 0.f;
#pragma unroll
    for (int i = 0; i < 16; i++) { v[i] = yr[lane + 32 * i]; s += v[i]; }
#pragma unroll
    for (int o = 16; o > 0; o >>= 1) s += __shfl_xor_sync(0xffffffffu, s, o);
    float mean = s * (1.0f / DM);
    float q = 0.f;
#pragma unroll
    for (int i = 0; i < 16; i++) { float d = v[i] - mean; q = fmaf(d, d, q); }
#pragma unroll
    for (int o = 16; o > 0; o >>= 1) q += __shfl_xor_sync(0xffffffffu, q, o);
    float inv = rsqrtf(q * (1.0f / DM) + 1e-5f);
#pragma unroll
    for (int i = 0; i < 16; i++) {
        int c = lane + 32 * i;
        out[(size_t)row * DM + c] = (v[i] - mean) * inv * lnw[c] + lnb[c];
    }
}

// ---------------------------------------------------------------------------
extern "C" void kernel_launch(void* const* d_in, const int* in_sizes, int n_in,
                              void* d_out, int out_size) {
    const float* x    = (const float*)d_in[0];
    const float* mask = (const float*)d_in[1];
    const float* plog = (const float*)d_in[2];
    const float* Wre  = (const float*)d_in[3];
    const float* Wim  = (const float*)d_in[4];
    const float* bre  = (const float*)d_in[5];
    const float* bim  = (const float*)d_in[6];
    const float* Wor  = (const float*)d_in[7];
    const float* Woi  = (const float*)d_in[8];
    const float* bor  = (const float*)d_in[9];
    // d_in[10] = b_out_im (unused: only real part survives)
    const float* lnw  = (const float*)d_in[11];
    const float* lnb  = (const float*)d_in[12];
    float* out = (float*)d_out;

    const int smem1 = 3 * (128 * 128 + 16384);  // 98304 (TM=128)
    cudaFuncSetAttribute(gemm_f16<DM, 1, 128>,
                         cudaFuncAttributeMaxDynamicSharedMemorySize, smem1);
    cudaFuncSetAttribute(gemm_f16<NTOT, 2, 128>,
                         cudaFuncAttributeMaxDynamicSharedMemorySize, smem1);

    // Launch order: scan_phase<1> sits at capture slot 4.
    cvt_x_kernel <<<(NTOK * DM / 4) / 256, 256>>>(x);
    cvt_wp_kernel<<<1025, 256>>>(Wre, Wim, Wor, Woi, plog, bre, bim);

    // GEMM1: h = (X @ [Wre/Wim interleaved]^T + b) * gamma  -> g_Hh (fp16)
    gemm_f16<DM, 1, 128><<<dim3(NTOK / 128, NTOT / 128), 128, smem1>>>(nullptr, nullptr);

    // chunked parallel scan (in place on g_Hh)
    scan_phase<1><<<BDIM * NCH * 8, 128>>>(mask);
    scan_combine<<<(BDIM * HID) / 128, 128>>>();
    scan_phase<2><<<BDIM * NCH * 8, 128>>>(mask);

    // GEMM2: y = H_interleaved @ [Wor,-Woi interleaved]^T + b_out_re + x  -> g_y
    gemm_f16<NTOT, 2, 128><<<dim3(NTOK / 128, DM / 128), 128, smem1>>>(bor, x);

    ln_kernel<<<NTOK / 8, 256>>>(lnw, lnb, out);
}